// round 14
// baseline (speedup 1.0000x reference)
#include <cuda_runtime.h>
#include <cuda_fp16.h>
#include <cstdint>
#include <cstddef>

#define BB   8
#define CIN  256
#define HWP  (120*160)   /* 19200 output plane size */
#define NSLOT 600        /* partial-stats slots per channel */

// ---------------- scratch (static device globals; no allocation) ----------------
__device__ float g_ybig[(size_t)BB * 256 * HWP]; // ch 0..127 conv1 raw, 128..255 shortcut raw
__device__ float g_y11 [(size_t)BB * 128 * HWP];
__device__ float g_y2  [(size_t)BB * 128 * HWP];
__device__ float g_ssA [256];   // (scale,shift) interleaved
__device__ float g_ssSC[256];
__device__ float g_ss11[256];
__device__ float g_ss2 [256];

// per-(channel, CTA-slot) partial sums for BN stats (written by conv epilogue)
__device__ float g_psum[256 * NSLOT];
__device__ float g_psq [256 * NSLOT];

// fp16 weights: [tap][co][ci]
__device__ __half g_wA [25 * 256 * 256];
__device__ __half g_w11[ 9 * 128 * 256];
__device__ __half g_w2 [ 9 * 128 * 128];

// fp16 activations, NHWC [b][pix][c]
__device__ __half g_xa [(size_t)BB *  4800 * 256];
__device__ __half g_cat[(size_t)BB * 19200 * 256];
__device__ __half g_a11[(size_t)BB * 19200 * 128];

__device__ __forceinline__ float* pickBuf(int s) {
    return s == 0 ? g_ybig : (s == 1 ? g_y11 : g_y2);
}
__device__ __forceinline__ float* pickSS(int s) {
    return s == 0 ? g_ssA : (s == 1 ? g_ssSC : (s == 2 ? g_ss11 : g_ss2));
}
__device__ __forceinline__ __half* pickW(int s) {
    return s == 0 ? g_wA : (s == 1 ? g_w11 : g_w2);
}
__device__ __forceinline__ __half* pickAct(int s) {
    return s == 0 ? g_xa : (s == 1 ? g_cat : g_a11);
}

// ---------------- tap tables ----------------
__constant__ int c_dy[5][9] = {
    {-1,-1,-1, 0,0,0, 1,1,1},
    {-1,-1,-1, 0,0,0, 1,1,1},
    {-1,-1, 0,0, 1,1, 0,0,0},
    { 0, 0, 0, 1,1,1, 0,0,0},
    { 0, 0, 1, 1, 0,0,0,0,0},
};
__constant__ int c_dx[5][9] = {
    {-1,0,1, -1,0,1, -1,0,1},
    {-1,0,1, -1,0,1, -1,0,1},
    { 0,1, 0,1, 0,1, 0,0,0},
    {-1,0,1, -1,0,1, 0,0,0},
    { 0,1, 0,1, 0,0,0,0,0},
};
__constant__ int c_wi[5][9] = {
    {0,1,2, 3,4,5, 6,7,8},
    {0,2,4, 10,12,14, 20,22,24},
    {1,3, 11,13, 21,23, 0,0,0},
    {5,7,9, 15,17,19, 0,0,0},
    {6,8, 16,18, 0,0,0,0,0},
};
__constant__ int c_cntz[4] = {9, 6, 6, 4};
__constant__ int c_pyz [4] = {0, 0, 1, 1};
__constant__ int c_pxz [4] = {0, 1, 0, 1};

// ---------------- PTX helpers ----------------
__device__ __forceinline__ uint32_t smem_u32(const void* p) {
    uint32_t a;
    asm("{ .reg .u64 t; cvta.to.shared.u64 t, %1; cvt.u32.u64 %0, t; }" : "=r"(a) : "l"(p));
    return a;
}
__device__ __forceinline__ void ldsm_x4(uint32_t* r, uint32_t addr) {
    asm volatile("ldmatrix.sync.aligned.m8n8.x4.shared.b16 {%0,%1,%2,%3}, [%4];"
                 : "=r"(r[0]), "=r"(r[1]), "=r"(r[2]), "=r"(r[3]) : "r"(addr));
}
__device__ __forceinline__ void mma_f16(float* d, const uint32_t* a, const uint32_t* b) {
    asm volatile("mma.sync.aligned.m16n8k16.row.col.f32.f16.f16.f32 "
                 "{%0,%1,%2,%3},{%4,%5,%6,%7},{%8,%9},{%0,%1,%2,%3};"
                 : "+f"(d[0]), "+f"(d[1]), "+f"(d[2]), "+f"(d[3])
                 : "r"(a[0]), "r"(a[1]), "r"(a[2]), "r"(a[3]), "r"(b[0]), "r"(b[1]));
}
__device__ __forceinline__ void cp16(uint32_t dst, const void* src, uint32_t sz) {
    asm volatile("cp.async.cg.shared.global [%0], [%1], 16, %2;"
                 :: "r"(dst), "l"(src), "r"(sz) : "memory");
}
__device__ __forceinline__ void cp_commit() {
    asm volatile("cp.async.commit_group;" ::: "memory");
}
__device__ __forceinline__ void cp_wait1() {
    asm volatile("cp.async.wait_group 1;" ::: "memory");
}

// ---------------- SMEM layout: header + 3 stages (48KB each) ----------------
#define OFF_SB    0                    /* int[256] */
#define OFF_SY    1024
#define OFF_SX    2048
#define OFF_STAGE 3072
#define STG_A     0                    /* 128co x 64ci fp16 = 16KB */
#define STG_B     16384                /* 256sp x 64ci fp16 = 32KB */
#define STAGE_BYTES 49152
#define NSTAGE    3
#define SMEM_BYTES (OFF_STAGE + NSTAGE * STAGE_BYTES)   /* 150528 -> 1 CTA/SM */

// ---------------------------------------------------------------------------
// Weight prep: fp32 [co][ci][taps] -> fp16 [tap][co][ci].
// ---------------------------------------------------------------------------
__global__ void prep_kernel(const float* __restrict__ s0, const float* __restrict__ s1,
                            int coT, int ciT, int taps, int sel)
{
    const int idx = blockIdx.x * 256 + threadIdx.x;
    const int total = taps * coT * ciT;
    if (idx >= total) return;
    const int ci = idx % ciT;
    const int co = (idx / ciT) % coT;
    const int tap = idx / (ciT * coT);
    const float* s = s0;
    int c = co;
    if (s1 != nullptr && co >= 128) { s = s1; c = co - 128; }
    const float v = s[((size_t)c * ciT + ci) * taps + tap];
    pickW(sel)[idx] = __float2half_rn(v);
}

// ---------------------------------------------------------------------------
// Activation prep: fp32 NCHW (virtual concat, optional fused BN+ReLU) ->
// fp16 NHWC. Tile = 64 pixels x 64 channels with smem transpose.
// ---------------------------------------------------------------------------
__global__ __launch_bounds__(256)
void actprep_kernel(int inASel, const float* __restrict__ inAExt,
                    const float* __restrict__ inB,
                    int strA, int strB, int split, int C, int HW,
                    int useBn, int ssSel, int dstSel)
{
    __shared__ __half s_t[64][72];
    const int tid = threadIdx.x;
    const int pix0 = blockIdx.x * 64;
    const int c0   = blockIdx.y * 64;
    const int b    = blockIdx.z;
    const float* inA = (inASel < 0) ? inAExt : pickBuf(inASel);
    const float* ss  = pickSS(ssSel);
    __half* dst = pickAct(dstSel);

    const int cSub = tid >> 6, pixL = tid & 63;
#pragma unroll 4
    for (int ci = 0; ci < 16; ci++) {
        const int cl = ci * 4 + cSub;
        const int c = c0 + cl;
        float v;
        if (c < split) {
            v = inA[((size_t)(b * strA + c)) * HW + pix0 + pixL];
            if (useBn) v = fmaxf(fmaf(v, ss[2 * c], ss[2 * c + 1]), 0.f);
        } else {
            v = inB[((size_t)(b * strB + (c - split))) * HW + pix0 + pixL];
        }
        s_t[pixL][cl] = __float2half_rn(v);
    }
    __syncthreads();
    const int chunk = tid & 7, pL0 = tid >> 3;
#pragma unroll
    for (int h = 0; h < 2; h++) {
        const int pL = pL0 + h * 32;
        const uint4 vh = *(const uint4*)&s_t[pL][chunk * 8];
        const size_t doff = (size_t)(b * HW + pix0 + pL) * C + c0 + chunk * 8;
        *(uint4*)(dst + doff) = vh;
    }
}

// ---------------------------------------------------------------------------
// conv-as-tap-GEMM via mma.sync fp16. D[128co][256sp] per CTA.
// 8 warps in 2(M)x4(N) grid, warp tile 64co x 64sp (128 accs/thread).
// 3-stage cp.async pipeline, one barrier/iter, 1 CTA/SM (smem-BW optimized).
// ---------------------------------------------------------------------------
__global__ __launch_bounds__(256, 1)
void conv_mma_kernel(
    int actSel, int C, int sH, int sW,
    int wSel, int coT,
    int multiSet, int tapSet, int tapCount,
    int outSel, int outBStride,
    int oyMul, int oyAdd, int oxMul, int oxAdd,
    int outW)
{
    extern __shared__ __align__(128) char smem[];
    const uint32_t sb = smem_u32(smem);
    int* s_bt = (int*)(smem + OFF_SB);
    int* s_yt = (int*)(smem + OFF_SY);
    int* s_xt = (int*)(smem + OFF_SX);

    const int tid = threadIdx.x;
    const int lane = tid & 31, wid = tid >> 5;
    const int wm = wid >> 2, wn = wid & 3;       // 2(M) x 4(N)
    const int inHW = sH * sW;
    const int outHW = HWP;
    const int chanOff = blockIdx.y * 128;

    int tapSetL = tapSet, tapCountL = tapCount, oyAddL = oyAdd, oxAddL = oxAdd;
    if (multiSet) {
        const int z = blockIdx.z;
        tapSetL = z + 1;
        tapCountL = c_cntz[z];
        oyAddL = c_pyz[z];
        oxAddL = c_pxz[z];
    }
    const int slot = blockIdx.z * gridDim.x + blockIdx.x;   // 0..599

    float* outP = pickBuf(outSel);
    const __half* act = pickAct(actSel);
    const __half* wgt = pickW(wSel);

    // 256 spatial positions for this CTA
    {
        const int s = blockIdx.x * 256 + tid;
        const int b = s / inHW; const int r = s - b * inHW;
        const int y = r / sW;
        s_bt[tid] = b; s_yt[tid] = y; s_xt[tid] = r - y * sW;
    }
    __syncthreads();

    // staging: B = 1 thread per sp row (8 x 16B); A = 2 threads per co row (4 x 16B)
    const int bS = s_bt[tid], yS = s_yt[tid], xS = s_xt[tid];
    const uint32_t bDst0 = sb + OFF_STAGE + STG_B + tid * 128;
    const int swzB = tid & 7;
    const int rowA = tid & 127, partA = tid >> 7;
    const uint32_t aDst0 = sb + OFF_STAGE + STG_A + rowA * 128;
    const int swzA = rowA & 7;
    const size_t wRowBase = (size_t)(chanOff + rowA) * C;

    float acc[4][8][4];
#pragma unroll
    for (int i = 0; i < 4; i++)
#pragma unroll
        for (int j = 0; j < 8; j++)
#pragma unroll
            for (int k = 0; k < 4; k++) acc[i][j][k] = 0.f;

    // ldmatrix lane addressing (XOR swizzle on 128B rows)
    const int sx = lane & 7;
    const uint32_t aRowBase = (uint32_t)(wm * 64 + (lane & 15)) * 128;
    const uint32_t bRowBase = (uint32_t)(wn * 64 + (lane & 7) + ((lane >> 4) << 3)) * 128;
    const int ka0 = lane >> 4;
    const int kb0 = (lane >> 3) & 1;

    const int nIter = (C >> 6) * tapCountL;

    auto stage = [&](int it, int s) {
        const int cbi = it / tapCountL;
        const int t   = it - cbi * tapCountL;
        const int cb  = cbi << 6;
        const int dy = c_dy[tapSetL][t], dx = c_dx[tapSetL][t], wi = c_wi[tapSetL][t];
        const uint32_t sOff = (uint32_t)s * STAGE_BYTES;
        // B: activation row for this thread's pixel, shifted by tap
        {
            const int yy = yS + dy, xx = xS + dx;
            const bool inb = ((unsigned)yy < (unsigned)sH) && ((unsigned)xx < (unsigned)sW);
            const __half* src = inb
                ? act + (size_t)(bS * inHW + yy * sW + xx) * C + cb
                : act;
            const uint32_t sz = inb ? 16u : 0u;
            const uint32_t d = bDst0 + sOff;
#pragma unroll
            for (int c8 = 0; c8 < 8; c8++)
                cp16(d + ((c8 ^ swzB) << 4), src + c8 * 8, sz);
        }
        // A: weight row (co = rowA) for this tap
        {
            const __half* src = wgt + (size_t)wi * coT * C + wRowBase + cb;
            const uint32_t d = aDst0 + sOff;
#pragma unroll
            for (int j = 0; j < 4; j++) {
                const int c8 = partA * 4 + j;
                cp16(d + ((c8 ^ swzA) << 4), src + c8 * 8, 16u);
            }
        }
    };

    stage(0, 0); cp_commit();
    stage(1, 1); cp_commit();

    int st = 0, st2 = 2;
    for (int it = 0; it < nIter; it++) {
        cp_wait1();
        __syncthreads();

        if (it + 2 < nIter) stage(it + 2, st2);
        cp_commit();

        const uint32_t stBase = sb + OFF_STAGE + (uint32_t)st * STAGE_BYTES;
        const uint32_t Abase = stBase + STG_A;
        const uint32_t Bbase = stBase + STG_B;
#pragma unroll
        for (int k = 0; k < 4; k++) {
            const uint32_t aOff = (uint32_t)(((ka0 + 2 * k) ^ sx) << 4);
            const uint32_t bOff = (uint32_t)(((kb0 + 2 * k) ^ sx) << 4);
            uint32_t a[4][4];
#pragma unroll
            for (int mf = 0; mf < 4; mf++)
                ldsm_x4(a[mf], Abase + aRowBase + mf * (16 * 128) + aOff);
            uint32_t bb[2][4];
            ldsm_x4(bb[0], Bbase + bRowBase + bOff);
#pragma unroll
            for (int nt = 0; nt < 4; nt++) {
                if (nt < 3)
                    ldsm_x4(bb[(nt + 1) & 1], Bbase + bRowBase + (nt + 1) * 2048 + bOff);
                const uint32_t* b = bb[nt & 1];
#pragma unroll
                for (int mf = 0; mf < 4; mf++) {
                    mma_f16(acc[mf][nt*2  ], a[mf], b);
                    mma_f16(acc[mf][nt*2+1], a[mf], b + 2);
                }
            }
        }
        st  = (st  == 2) ? 0 : st  + 1;
        st2 = (st2 == 2) ? 0 : st2 + 1;
    }

    // ---- epilogue: registers -> global (fp32 NCHW scratch), inline addresses ----
    const int coW = chanOff + wm * 64 + (lane >> 2);
#pragma unroll
    for (int j = 0; j < 8; j++) {
#pragma unroll
        for (int e = 0; e < 2; e++) {
            const int spi = wn * 64 + j * 8 + (lane & 3) * 2 + e;
            const int b = s_bt[spi];
            const int oy = s_yt[spi] * oyMul + oyAddL;
            const int ox = s_xt[spi] * oxMul + oxAddL;
            const uint32_t o = (uint32_t)(b * outBStride) * (uint32_t)outHW
                             + (uint32_t)(oy * outW + ox);
#pragma unroll
            for (int mf = 0; mf < 4; mf++) {
                const size_t c0 = (size_t)(coW + mf * 16) * outHW;
                outP[c0 + o]                     = acc[mf][j][e];
                outP[c0 + (size_t)8 * outHW + o] = acc[mf][j][2 + e];
            }
        }
    }

    // ---- deterministic per-(co, CTA) BN partials ----
    float ps[8], pq[8];
#pragma unroll
    for (int mf = 0; mf < 4; mf++)
#pragma unroll
        for (int h = 0; h < 2; h++) {
            float s = 0.f, q = 0.f;
#pragma unroll
            for (int j = 0; j < 8; j++)
#pragma unroll
                for (int e = 0; e < 2; e++) {
                    const float v = acc[mf][j][h * 2 + e];
                    s += v; q += v * v;
                }
            ps[mf * 2 + h] = s; pq[mf * 2 + h] = q;
        }
#pragma unroll
    for (int i = 0; i < 8; i++) {
        ps[i] += __shfl_xor_sync(0xffffffffu, ps[i], 1);
        ps[i] += __shfl_xor_sync(0xffffffffu, ps[i], 2);
        pq[i] += __shfl_xor_sync(0xffffffffu, pq[i], 1);
        pq[i] += __shfl_xor_sync(0xffffffffu, pq[i], 2);
    }
    __syncthreads();    // mainloop smem reads done; reuse stage area
    float* sred = (float*)(smem + OFF_STAGE);          // [4][128]
    float* qred = (float*)(smem + OFF_STAGE + 2048);   // [4][128]
    if ((lane & 3) == 0) {
        const int l4 = lane >> 2;
#pragma unroll
        for (int mf = 0; mf < 4; mf++)
#pragma unroll
            for (int h = 0; h < 2; h++) {
                const int col = wm * 64 + mf * 16 + h * 8 + l4;
                sred[wn * 128 + col] = ps[mf * 2 + h];
                qred[wn * 128 + col] = pq[mf * 2 + h];
            }
    }
    __syncthreads();
    if (tid < 128) {
        const float s = sred[tid] + sred[128 + tid] + sred[256 + tid] + sred[384 + tid];
        const float q = qred[tid] + qred[128 + tid] + qred[256 + tid] + qred[384 + tid];
        g_psum[(size_t)(chanOff + tid) * NSLOT + slot] = s;
        g_psq [(size_t)(chanOff + tid) * NSLOT + slot] = q;
    }
}

// ---------------------------------------------------------------------------
// Combine per-CTA partials -> (scale, shift). One block per channel.
// ---------------------------------------------------------------------------
__global__ void combine_kernel(int chanOff,
                               const float* __restrict__ gamma,
                               const float* __restrict__ beta,
                               int ssSel)
{
    float* ss = pickSS(ssSel);
    const int c = blockIdx.x;
    const int tid = threadIdx.x;
    const float* psp = g_psum + (size_t)(chanOff + c) * NSLOT;
    const float* pqp = g_psq  + (size_t)(chanOff + c) * NSLOT;
    float s = 0.f, q = 0.f;
    for (int i = tid; i < NSLOT; i += 256) { s += psp[i]; q += pqp[i]; }
    __shared__ float red[512];
    red[tid] = s; red[256 + tid] = q;
    __syncthreads();
    for (int off = 128; off > 0; off >>= 1) {
        if (tid < off) {
            red[tid]       += red[tid + off];
            red[256 + tid] += red[256 + tid + off];
        }
        __syncthreads();
    }
    if (tid == 0) {
        const float N = (float)(BB * HWP);
        float mean = red[0] / N;
        float var  = red[256] / N - mean * mean;
        float inv  = rsqrtf(var + 1e-5f);
        float scv  = gamma[c] * inv;
        ss[2 * c]     = scv;
        ss[2 * c + 1] = beta[c] - mean * scv;
    }
}

// out = relu(bn(y2) + bn(ysc))
__global__ void final_kernel(float* __restrict__ out)
{
    const int t  = blockIdx.x * 256 + threadIdx.x;
    const int p  = t % 4800;
    const int bc = t / 4800;
    const int b = bc >> 7, c = bc & 127;
    const float s2  = g_ss2[2 * c],  t2  = g_ss2[2 * c + 1];
    const float ssc = g_ssSC[2 * c], tsc = g_ssSC[2 * c + 1];
    const float4 a = ((const float4*)(g_y2   + (size_t)(b * 128 + c) * HWP))[p];
    const float4 d = ((const float4*)(g_ybig + (size_t)(b * 256 + 128 + c) * HWP))[p];
    float4 o;
    o.x = fmaxf(fmaf(a.x, s2, t2) + fmaf(d.x, ssc, tsc), 0.f);
    o.y = fmaxf(fmaf(a.y, s2, t2) + fmaf(d.y, ssc, tsc), 0.f);
    o.z = fmaxf(fmaf(a.z, s2, t2) + fmaf(d.z, ssc, tsc), 0.f);
    o.w = fmaxf(fmaf(a.w, s2, t2) + fmaf(d.w, ssc, tsc), 0.f);
    ((float4*)out)[t] = o;
}

// ---------------------------------------------------------------------------
extern "C" void kernel_launch(void* const* d_in, const int* in_sizes, int n_in,
                              void* d_out, int out_size)
{
    const float* x    = (const float*)d_in[0];
    const float* side = (const float*)d_in[1];
    const float* w1   = (const float*)d_in[2];
    const float* g1   = (const float*)d_in[3];
    const float* b1   = (const float*)d_in[4];
    const float* w11  = (const float*)d_in[5];
    const float* g11  = (const float*)d_in[6];
    const float* b11  = (const float*)d_in[7];
    const float* w2   = (const float*)d_in[8];
    const float* g2   = (const float*)d_in[9];
    const float* b2   = (const float*)d_in[10];
    const float* wsc  = (const float*)d_in[11];
    const float* gsc  = (const float*)d_in[12];
    const float* bsc  = (const float*)d_in[13];
    float* out = (float*)d_out;

    cudaFuncSetAttribute(conv_mma_kernel,
                         cudaFuncAttributeMaxDynamicSharedMemorySize, SMEM_BYTES);

    // 0) weights -> fp16 [tap][co][ci]
    prep_kernel<<<(25*256*256 + 255)/256, 256>>>(w1, wsc, 256, 256, 25, 0);
    prep_kernel<<<( 9*128*256 + 255)/256, 256>>>(w11, nullptr, 128, 256, 9, 1);
    prep_kernel<<<( 9*128*128 + 255)/256, 256>>>(w2,  nullptr, 128, 128, 9, 2);

    // 0b) x -> fp16 NHWC
    {
        dim3 g(4800/64, 256/64, BB);
        actprep_kernel<<<g, 256>>>(-1, x, nullptr, CIN, 0, CIN, 256, 4800, 0, 0, 0);
    }

    // 1) sparse 5x5 conv, all 4 parity sets in ONE launch (z = set-1).
    {
        dim3 gA(150, 2, 4);
        conv_mma_kernel<<<gA, 256, SMEM_BYTES>>>(
            /*actSel*/0, 256, 60, 80,
            /*wSel*/0, /*coT*/256, /*multiSet*/1, 0, 0,
            /*outSel*/0, 256,
            2, 0, 2, 0, 160);
    }

    // 2) BN stats from conv partials (both halves)
    combine_kernel<<<128, 256>>>(0,   g1,  b1,  0);
    combine_kernel<<<128, 256>>>(128, gsc, bsc, 1);

    // 2b) concat input: bn+relu(y1) ch 0..127, side ch 128..255 -> fp16 NHWC
    {
        dim3 g(19200/64, 256/64, BB);
        actprep_kernel<<<g, 256>>>(0, nullptr, side, 256, 128, 128, 256, 19200, 1, 0, 1);
    }

    // 3) conv3x3 over concat -> y11
    dim3 g3(600, 1, 1);
    conv_mma_kernel<<<g3, 256, SMEM_BYTES>>>(
        /*actSel*/1, 256, 120, 160,
        /*wSel*/1, /*coT*/128, /*multiSet*/0, 0, 9,
        /*outSel*/1, 128,
        1, 0, 1, 0, 160);

    // 4) BN stats on y11 from partials; a11 = relu(bn(y11)) -> fp16 NHWC
    combine_kernel<<<128, 256>>>(0, g11, b11, 2);
    {
        dim3 g(19200/64, 128/64, BB);
        actprep_kernel<<<g, 256>>>(1, nullptr, nullptr, 128, 0, 128, 128, 19200, 1, 2, 2);
    }

    // 5) conv3x3 (Cin=128) -> y2
    conv_mma_kernel<<<g3, 256, SMEM_BYTES>>>(
        /*actSel*/2, 128, 120, 160,
        /*wSel*/2, /*coT*/128, /*multiSet*/0, 0, 9,
        /*outSel*/2, 128,
        1, 0, 1, 0, 160);

    // 6) BN stats for y2 from partials; final fuse: relu(bn(y2) + bn(ysc))
    combine_kernel<<<128, 256>>>(0, g2, b2, 3);
    final_kernel<<<19200, 256>>>(out);
}

// round 15
// speedup vs baseline: 1.3366x; 1.3366x over previous
#include <cuda_runtime.h>
#include <cuda_fp16.h>
#include <cstdint>
#include <cstddef>

#define BB   8
#define CIN  256
#define HWP  (120*160)   /* 19200 output plane size */
#define NSLOT 1200       /* partial-stats slots per channel (all convs) */

// ---------------- scratch (static device globals; no allocation) ----------------
__device__ float g_ybig[(size_t)BB * 256 * HWP]; // ch 0..127 conv1 raw, 128..255 shortcut raw
__device__ float g_y11 [(size_t)BB * 128 * HWP];
__device__ float g_y2  [(size_t)BB * 128 * HWP];
__device__ float g_ssA [256];   // (scale,shift) interleaved
__device__ float g_ssSC[256];
__device__ float g_ss11[256];
__device__ float g_ss2 [256];

// per-(channel, CTA-slot) partial sums for BN stats (written by conv epilogue)
__device__ float g_psum[256 * NSLOT];
__device__ float g_psq [256 * NSLOT];

// fp16 weights: [tap][co][ci]
__device__ __half g_wA [25 * 256 * 256];
__device__ __half g_w11[ 9 * 128 * 256];
__device__ __half g_w2 [ 9 * 128 * 128];

// fp16 activations, NHWC [b][pix][c]
__device__ __half g_xa [(size_t)BB *  4800 * 256];
__device__ __half g_cat[(size_t)BB * 19200 * 256];
__device__ __half g_a11[(size_t)BB * 19200 * 128];

__device__ __forceinline__ float* pickBuf(int s) {
    return s == 0 ? g_ybig : (s == 1 ? g_y11 : g_y2);
}
__device__ __forceinline__ float* pickSS(int s) {
    return s == 0 ? g_ssA : (s == 1 ? g_ssSC : (s == 2 ? g_ss11 : g_ss2));
}
__device__ __forceinline__ __half* pickW(int s) {
    return s == 0 ? g_wA : (s == 1 ? g_w11 : g_w2);
}
__device__ __forceinline__ __half* pickAct(int s) {
    return s == 0 ? g_xa : (s == 1 ? g_cat : g_a11);
}

// ---------------- tap tables ----------------
__constant__ int c_dy[5][9] = {
    {-1,-1,-1, 0,0,0, 1,1,1},
    {-1,-1,-1, 0,0,0, 1,1,1},
    {-1,-1, 0,0, 1,1, 0,0,0},
    { 0, 0, 0, 1,1,1, 0,0,0},
    { 0, 0, 1, 1, 0,0,0,0,0},
};
__constant__ int c_dx[5][9] = {
    {-1,0,1, -1,0,1, -1,0,1},
    {-1,0,1, -1,0,1, -1,0,1},
    { 0,1, 0,1, 0,1, 0,0,0},
    {-1,0,1, -1,0,1, 0,0,0},
    { 0,1, 0,1, 0,0,0,0,0},
};
__constant__ int c_wi[5][9] = {
    {0,1,2, 3,4,5, 6,7,8},
    {0,2,4, 10,12,14, 20,22,24},
    {1,3, 11,13, 21,23, 0,0,0},
    {5,7,9, 15,17,19, 0,0,0},
    {6,8, 16,18, 0,0,0,0,0},
};
__constant__ int c_cntz[4] = {9, 6, 6, 4};
__constant__ int c_pyz [4] = {0, 0, 1, 1};
__constant__ int c_pxz [4] = {0, 1, 0, 1};

// ---------------- PTX helpers (sm_80+ baseline — compiles at sm_100) ----------------
__device__ __forceinline__ uint32_t smem_u32(const void* p) {
    uint32_t a;
    asm("{ .reg .u64 t; cvta.to.shared.u64 t, %1; cvt.u32.u64 %0, t; }" : "=r"(a) : "l"(p));
    return a;
}
__device__ __forceinline__ void ldsm_x4(uint32_t* r, uint32_t addr) {
    asm volatile("ldmatrix.sync.aligned.m8n8.x4.shared.b16 {%0,%1,%2,%3}, [%4];"
                 : "=r"(r[0]), "=r"(r[1]), "=r"(r[2]), "=r"(r[3]) : "r"(addr));
}
__device__ __forceinline__ void mma_f16(float* d, const uint32_t* a, const uint32_t* b) {
    asm volatile("mma.sync.aligned.m16n8k16.row.col.f32.f16.f16.f32 "
                 "{%0,%1,%2,%3},{%4,%5,%6,%7},{%8,%9},{%0,%1,%2,%3};"
                 : "+f"(d[0]), "+f"(d[1]), "+f"(d[2]), "+f"(d[3])
                 : "r"(a[0]), "r"(a[1]), "r"(a[2]), "r"(a[3]), "r"(b[0]), "r"(b[1]));
}
__device__ __forceinline__ void cp16(uint32_t dst, const void* src, uint32_t sz) {
    asm volatile("cp.async.cg.shared.global [%0], [%1], 16, %2;"
                 :: "r"(dst), "l"(src), "r"(sz) : "memory");
}
__device__ __forceinline__ void cp_commit() {
    asm volatile("cp.async.commit_group;" ::: "memory");
}
__device__ __forceinline__ void cp_wait1() {
    asm volatile("cp.async.wait_group 1;" ::: "memory");
}

// ---------------- SMEM layout: header + 3 pipeline stages (32KB each) ----------------
#define OFF_SB    0                    /* int[128] */
#define OFF_SY    512
#define OFF_SX    1024
#define OFF_STAGE 2048
#define STG_A     0                    /* 128co x 64ci fp16 = 16KB */
#define STG_B     16384                /* 128sp x 64ci fp16 = 16KB */
#define STAGE_BYTES 32768
#define NSTAGE    3
#define SMEM_BYTES (OFF_STAGE + NSTAGE * STAGE_BYTES)   /* 100352 -> 2 CTAs/SM */

// ---------------------------------------------------------------------------
// Weight prep: fp32 [co][ci][taps] -> fp16 [tap][co][ci].
// ---------------------------------------------------------------------------
__global__ void prep_kernel(const float* __restrict__ s0, const float* __restrict__ s1,
                            int coT, int ciT, int taps, int sel)
{
    const int idx = blockIdx.x * 256 + threadIdx.x;
    const int total = taps * coT * ciT;
    if (idx >= total) return;
    const int ci = idx % ciT;
    const int co = (idx / ciT) % coT;
    const int tap = idx / (ciT * coT);
    const float* s = s0;
    int c = co;
    if (s1 != nullptr && co >= 128) { s = s1; c = co - 128; }
    const float v = s[((size_t)c * ciT + ci) * taps + tap];
    pickW(sel)[idx] = __float2half_rn(v);
}

// ---------------------------------------------------------------------------
// Activation prep: fp32 NCHW (virtual concat, optional fused BN+ReLU) ->
// fp16 NHWC. Tile = 64 pixels x 64 channels with smem transpose.
// ---------------------------------------------------------------------------
__global__ __launch_bounds__(256)
void actprep_kernel(int inASel, const float* __restrict__ inAExt,
                    const float* __restrict__ inB,
                    int strA, int strB, int split, int C, int HW,
                    int useBn, int ssSel, int dstSel)
{
    __shared__ __half s_t[64][72];
    const int tid = threadIdx.x;
    const int pix0 = blockIdx.x * 64;
    const int c0   = blockIdx.y * 64;
    const int b    = blockIdx.z;
    const float* inA = (inASel < 0) ? inAExt : pickBuf(inASel);
    const float* ss  = pickSS(ssSel);
    __half* dst = pickAct(dstSel);

    const int cSub = tid >> 6, pixL = tid & 63;
#pragma unroll 4
    for (int ci = 0; ci < 16; ci++) {
        const int cl = ci * 4 + cSub;
        const int c = c0 + cl;
        float v;
        if (c < split) {
            v = inA[((size_t)(b * strA + c)) * HW + pix0 + pixL];
            if (useBn) v = fmaxf(fmaf(v, ss[2 * c], ss[2 * c + 1]), 0.f);
        } else {
            v = inB[((size_t)(b * strB + (c - split))) * HW + pix0 + pixL];
        }
        s_t[pixL][cl] = __float2half_rn(v);
    }
    __syncthreads();
    const int chunk = tid & 7, pL0 = tid >> 3;
#pragma unroll
    for (int h = 0; h < 2; h++) {
        const int pL = pL0 + h * 32;
        const uint4 vh = *(const uint4*)&s_t[pL][chunk * 8];
        const size_t doff = (size_t)(b * HW + pix0 + pL) * C + c0 + chunk * 8;
        *(uint4*)(dst + doff) = vh;
    }
}

// ---------------------------------------------------------------------------
// conv-as-tap-GEMM via mma.sync fp16 (single pass, fp32 accum).
// D[128 co][128 sp] per CTA, 8 warps 4(M)x2(N). 3-stage cp.async pipeline
// (depth-2 prefetch), one barrier per iteration, 2 CTAs/SM.
// A fragments double-buffered ACROSS k-groups; B fragments within a k-group.
// ---------------------------------------------------------------------------
__global__ __launch_bounds__(256, 2)
void conv_mma_kernel(
    int actSel, int C, int sH, int sW,
    int wSel, int coT,
    int multiSet, int tapSet, int tapCount,
    int outSel, int outBStride,
    int oyMul, int oyAdd, int oxMul, int oxAdd,
    int outW)
{
    extern __shared__ __align__(128) char smem[];
    const uint32_t sb = smem_u32(smem);
    int* s_bt = (int*)(smem + OFF_SB);
    int* s_yt = (int*)(smem + OFF_SY);
    int* s_xt = (int*)(smem + OFF_SX);

    const int tid = threadIdx.x;
    const int lane = tid & 31, wid = tid >> 5;
    const int wm = wid >> 1, wn = wid & 1;
    const int inHW = sH * sW;
    const int outHW = HWP;
    const int chanOff = blockIdx.y * 128;

    int tapSetL = tapSet, tapCountL = tapCount, oyAddL = oyAdd, oxAddL = oxAdd;
    if (multiSet) {
        const int z = blockIdx.z;
        tapSetL = z + 1;
        tapCountL = c_cntz[z];
        oyAddL = c_pyz[z];
        oxAddL = c_pxz[z];
    }
    const int slot = blockIdx.z * gridDim.x + blockIdx.x;   // 0..1199

    float* outP = pickBuf(outSel);
    const __half* act = pickAct(actSel);
    const __half* wgt = pickW(wSel);

    if (tid < 128) {
        const int s = blockIdx.x * 128 + tid;
        const int b = s / inHW; const int r = s - b * inHW;
        const int y = r / sW;
        s_bt[tid] = b; s_yt[tid] = y; s_xt[tid] = r - y * sW;
    }
    __syncthreads();

    // staging mapping: 2 threads per row, 4 x 16B chunks each (A and B alike)
    const int rowS = tid >> 1, partS = tid & 1;
    const int bS = s_bt[rowS], yS = s_yt[rowS], xS = s_xt[rowS];
    const uint32_t bDst0 = sb + OFF_STAGE + STG_B + rowS * 128;
    const uint32_t aDst0 = sb + OFF_STAGE + STG_A + rowS * 128;
    const int swzS = rowS & 7;
    const size_t wRowBase = (size_t)(chanOff + rowS) * C;

    float acc[2][8][4];
#pragma unroll
    for (int i = 0; i < 2; i++)
#pragma unroll
        for (int j = 0; j < 8; j++)
#pragma unroll
            for (int k = 0; k < 4; k++) acc[i][j][k] = 0.f;

    // ldmatrix lane addressing (XOR swizzle on 128B rows)
    const int sx = lane & 7;
    const uint32_t aRowBase = (uint32_t)(wm * 32 + (lane & 15)) * 128;
    const uint32_t bRowBase = (uint32_t)(wn * 64 + (lane & 7) + ((lane >> 4) << 3)) * 128;
    const int ka0 = lane >> 4;
    const int kb0 = (lane >> 3) & 1;

    const int nIter = (C >> 6) * tapCountL;

    // ---- staging issue for iteration `it` into stage buffer `s` (0..2) ----
    auto stage = [&](int it, int s) {
        const int cbi = it / tapCountL;
        const int t   = it - cbi * tapCountL;
        const int cb  = cbi << 6;
        const int dy = c_dy[tapSetL][t], dx = c_dx[tapSetL][t], wi = c_wi[tapSetL][t];
        const uint32_t sOff = (uint32_t)s * STAGE_BYTES;
        // B: fp16 activation row for pixel rowS shifted by tap
        {
            const int yy = yS + dy, xx = xS + dx;
            const bool inb = ((unsigned)yy < (unsigned)sH) && ((unsigned)xx < (unsigned)sW);
            const __half* src = inb
                ? act + (size_t)(bS * inHW + yy * sW + xx) * C + cb
                : act;
            const uint32_t sz = inb ? 16u : 0u;
            const uint32_t d = bDst0 + sOff;
#pragma unroll
            for (int j = 0; j < 4; j++) {
                const int c8 = partS * 4 + j;
                cp16(d + ((c8 ^ swzS) << 4), src + c8 * 8, sz);
            }
        }
        // A: weight row (co = rowS) for this tap
        {
            const __half* src = wgt + (size_t)wi * coT * C + wRowBase + cb;
            const uint32_t d = aDst0 + sOff;
#pragma unroll
            for (int j = 0; j < 4; j++) {
                const int c8 = partS * 4 + j;
                cp16(d + ((c8 ^ swzS) << 4), src + c8 * 8, 16u);
            }
        }
    };

    // prologue: stage iters 0 and 1 (nIter >= 16 always)
    stage(0, 0); cp_commit();
    stage(1, 1); cp_commit();

    int st = 0;          // it % 3
    int st2 = 2;         // (it+2) % 3
    for (int it = 0; it < nIter; it++) {
        cp_wait1();          // group `it` complete (group it+1 still in flight)
        __syncthreads();     // data visible; all warps done with MMA(it-1)

        // depth-2 prefetch into buffer (it+2)%3 (last read by MMA(it-1))
        if (it + 2 < nIter) stage(it + 2, st2);
        cp_commit();         // possibly-empty group keeps the count uniform

        const uint32_t stBase = sb + OFF_STAGE + (uint32_t)st * STAGE_BYTES;
        const uint32_t Abase = stBase + STG_A;
        const uint32_t Bbase = stBase + STG_B;

        // A fragments double-buffered across k-groups
        uint32_t aA[2][4], aB[2][4];
        {
            const uint32_t aOff0 = (uint32_t)((ka0 ^ sx) << 4);
            ldsm_x4(aA[0], Abase + aRowBase + aOff0);
            ldsm_x4(aB[0], Abase + aRowBase + 16 * 128 + aOff0);
        }
#pragma unroll
        for (int k = 0; k < 4; k++) {
            const int cur = k & 1, nxt = cur ^ 1;
            if (k < 3) {
                const uint32_t aOffN = (uint32_t)(((ka0 + 2 * (k + 1)) ^ sx) << 4);
                ldsm_x4(aA[nxt], Abase + aRowBase + aOffN);
                ldsm_x4(aB[nxt], Abase + aRowBase + 16 * 128 + aOffN);
            }
            const uint32_t bOff = (uint32_t)(((kb0 + 2 * k) ^ sx) << 4);
            uint32_t bb[2][4];
            ldsm_x4(bb[0], Bbase + bRowBase + bOff);
#pragma unroll
            for (int tt = 0; tt < 4; tt++) {
                if (tt < 3)
                    ldsm_x4(bb[(tt + 1) & 1], Bbase + bRowBase + (tt + 1) * 2048 + bOff);
                const uint32_t* b = bb[tt & 1];
                mma_f16(acc[0][tt*2  ], aA[cur], b);
                mma_f16(acc[0][tt*2+1], aA[cur], b + 2);
                mma_f16(acc[1][tt*2  ], aB[cur], b);
                mma_f16(acc[1][tt*2+1], aB[cur], b + 2);
            }
        }
        st  = (st  == 2) ? 0 : st  + 1;
        st2 = (st2 == 2) ? 0 : st2 + 1;
    }

    // ---- epilogue: registers -> global (fp32 NCHW scratch) ----
    uint32_t off[16];
#pragma unroll
    for (int i = 0; i < 16; i++) {
        const int nf = i >> 1, e = i & 1;
        const int spi = wn * 64 + nf * 8 + (lane & 3) * 2 + e;
        const int b = s_bt[spi];
        const int oy = s_yt[spi] * oyMul + oyAddL;
        const int ox = s_xt[spi] * oxMul + oxAddL;
        off[i] = (uint32_t)(b * outBStride) * (uint32_t)outHW
               + (uint32_t)(oy * outW + ox);
    }
    const int coBase = chanOff + wm * 32 + (lane >> 2);
#pragma unroll
    for (int mi = 0; mi < 2; mi++) {
        const size_t cOff0 = (size_t)(coBase + mi * 16) * outHW;
        const size_t cOff8 = cOff0 + (size_t)8 * outHW;
#pragma unroll
        for (int nf = 0; nf < 8; nf++) {
            outP[cOff0 + off[nf*2  ]] = acc[mi][nf][0];
            outP[cOff0 + off[nf*2+1]] = acc[mi][nf][1];
            outP[cOff8 + off[nf*2  ]] = acc[mi][nf][2];
            outP[cOff8 + off[nf*2+1]] = acc[mi][nf][3];
        }
    }

    // ---- deterministic per-(co, CTA) BN partials: sum & sumsq ----
    float ps[4], pq[4];
#pragma unroll
    for (int mi = 0; mi < 2; mi++)
#pragma unroll
        for (int h = 0; h < 2; h++) {
            float s = 0.f, q = 0.f;
#pragma unroll
            for (int nf = 0; nf < 8; nf++)
#pragma unroll
                for (int e = 0; e < 2; e++) {
                    const float v = acc[mi][nf][h * 2 + e];
                    s += v; q += v * v;
                }
            ps[mi * 2 + h] = s; pq[mi * 2 + h] = q;
        }
#pragma unroll
    for (int i = 0; i < 4; i++) {
        ps[i] += __shfl_xor_sync(0xffffffffu, ps[i], 1);
        ps[i] += __shfl_xor_sync(0xffffffffu, ps[i], 2);
        pq[i] += __shfl_xor_sync(0xffffffffu, pq[i], 1);
        pq[i] += __shfl_xor_sync(0xffffffffu, pq[i], 2);
    }
    __syncthreads();    // mainloop smem reads done; reuse stage 0 as scratch
    float* sred = (float*)(smem + OFF_STAGE);          // [2][128]
    float* qred = (float*)(smem + OFF_STAGE + 1024);   // [2][128]
    if ((lane & 3) == 0) {
        const int l4 = lane >> 2;
#pragma unroll
        for (int mi = 0; mi < 2; mi++)
#pragma unroll
            for (int h = 0; h < 2; h++) {
                const int col = wm * 32 + l4 + mi * 16 + h * 8;
                sred[wn * 128 + col] = ps[mi * 2 + h];
                qred[wn * 128 + col] = pq[mi * 2 + h];
            }
    }
    __syncthreads();
    if (tid < 128) {
        const float s = sred[tid] + sred[128 + tid];
        const float q = qred[tid] + qred[128 + tid];
        g_psum[(size_t)(chanOff + tid) * NSLOT + slot] = s;
        g_psq [(size_t)(chanOff + tid) * NSLOT + slot] = q;
    }
}

// ---------------------------------------------------------------------------
// Combine per-CTA partials -> (scale, shift). One block per channel.
// ---------------------------------------------------------------------------
__global__ void combine_kernel(int chanOff,
                               const float* __restrict__ gamma,
                               const float* __restrict__ beta,
                               int ssSel)
{
    float* ss = pickSS(ssSel);
    const int c = blockIdx.x;
    const int tid = threadIdx.x;
    const float* psp = g_psum + (size_t)(chanOff + c) * NSLOT;
    const float* pqp = g_psq  + (size_t)(chanOff + c) * NSLOT;
    float s = 0.f, q = 0.f;
    for (int i = tid; i < NSLOT; i += 256) { s += psp[i]; q += pqp[i]; }
    __shared__ float red[512];
    red[tid] = s; red[256 + tid] = q;
    __syncthreads();
    for (int off = 128; off > 0; off >>= 1) {
        if (tid < off) {
            red[tid]       += red[tid + off];
            red[256 + tid] += red[256 + tid + off];
        }
        __syncthreads();
    }
    if (tid == 0) {
        const float N = (float)(BB * HWP);
        float mean = red[0] / N;
        float var  = red[256] / N - mean * mean;
        float inv  = rsqrtf(var + 1e-5f);
        float scv  = gamma[c] * inv;
        ss[2 * c]     = scv;
        ss[2 * c + 1] = beta[c] - mean * scv;
    }
}

// out = relu(bn(y2) + bn(ysc))
__global__ void final_kernel(float* __restrict__ out)
{
    const int t  = blockIdx.x * 256 + threadIdx.x;
    const int p  = t % 4800;
    const int bc = t / 4800;
    const int b = bc >> 7, c = bc & 127;
    const float s2  = g_ss2[2 * c],  t2  = g_ss2[2 * c + 1];
    const float ssc = g_ssSC[2 * c], tsc = g_ssSC[2 * c + 1];
    const float4 a = ((const float4*)(g_y2   + (size_t)(b * 128 + c) * HWP))[p];
    const float4 d = ((const float4*)(g_ybig + (size_t)(b * 256 + 128 + c) * HWP))[p];
    float4 o;
    o.x = fmaxf(fmaf(a.x, s2, t2) + fmaf(d.x, ssc, tsc), 0.f);
    o.y = fmaxf(fmaf(a.y, s2, t2) + fmaf(d.y, ssc, tsc), 0.f);
    o.z = fmaxf(fmaf(a.z, s2, t2) + fmaf(d.z, ssc, tsc), 0.f);
    o.w = fmaxf(fmaf(a.w, s2, t2) + fmaf(d.w, ssc, tsc), 0.f);
    ((float4*)out)[t] = o;
}

// ---------------------------------------------------------------------------
extern "C" void kernel_launch(void* const* d_in, const int* in_sizes, int n_in,
                              void* d_out, int out_size)
{
    const float* x    = (const float*)d_in[0];
    const float* side = (const float*)d_in[1];
    const float* w1   = (const float*)d_in[2];
    const float* g1   = (const float*)d_in[3];
    const float* b1   = (const float*)d_in[4];
    const float* w11  = (const float*)d_in[5];
    const float* g11  = (const float*)d_in[6];
    const float* b11  = (const float*)d_in[7];
    const float* w2   = (const float*)d_in[8];
    const float* g2   = (const float*)d_in[9];
    const float* b2   = (const float*)d_in[10];
    const float* wsc  = (const float*)d_in[11];
    const float* gsc  = (const float*)d_in[12];
    const float* bsc  = (const float*)d_in[13];
    float* out = (float*)d_out;

    cudaFuncSetAttribute(conv_mma_kernel,
                         cudaFuncAttributeMaxDynamicSharedMemorySize, SMEM_BYTES);

    // 0) weights -> fp16 [tap][co][ci]
    prep_kernel<<<(25*256*256 + 255)/256, 256>>>(w1, wsc, 256, 256, 25, 0);
    prep_kernel<<<( 9*128*256 + 255)/256, 256>>>(w11, nullptr, 128, 256, 9, 1);
    prep_kernel<<<( 9*128*128 + 255)/256, 256>>>(w2,  nullptr, 128, 128, 9, 2);

    // 0b) x -> fp16 NHWC
    {
        dim3 g(4800/64, 256/64, BB);
        actprep_kernel<<<g, 256>>>(-1, x, nullptr, CIN, 0, CIN, 256, 4800, 0, 0, 0);
    }

    // 1) sparse 5x5 conv, all 4 parity sets in ONE launch (z = set-1).
    {
        dim3 gA(300, 2, 4);
        conv_mma_kernel<<<gA, 256, SMEM_BYTES>>>(
            /*actSel*/0, 256, 60, 80,
            /*wSel*/0, /*coT*/256, /*multiSet*/1, 0, 0,
            /*outSel*/0, 256,
            2, 0, 2, 0, 160);
    }

    // 2) BN stats from conv partials (both halves)
    combine_kernel<<<128, 256>>>(0,   g1,  b1,  0);
    combine_kernel<<<128, 256>>>(128, gsc, bsc, 1);

    // 2b) concat input: bn+relu(y1) ch 0..127, side ch 128..255 -> fp16 NHWC
    {
        dim3 g(19200/64, 256/64, BB);
        actprep_kernel<<<g, 256>>>(0, nullptr, side, 256, 128, 128, 256, 19200, 1, 0, 1);
    }

    // 3) conv3x3 over concat -> y11
    dim3 g3(1200, 1, 1);
    conv_mma_kernel<<<g3, 256, SMEM_BYTES>>>(
        /*actSel*/1, 256, 120, 160,
        /*wSel*/1, /*coT*/128, /*multiSet*/0, 0, 9,
        /*outSel*/1, 128,
        1, 0, 1, 0, 160);

    // 4) BN stats on y11 from partials; a11 = relu(bn(y11)) -> fp16 NHWC
    combine_kernel<<<128, 256>>>(0, g11, b11, 2);
    {
        dim3 g(19200/64, 128/64, BB);
        actprep_kernel<<<g, 256>>>(1, nullptr, nullptr, 128, 0, 128, 128, 19200, 1, 2, 2);
    }

    // 5) conv3x3 (Cin=128) -> y2
    conv_mma_kernel<<<g3, 256, SMEM_BYTES>>>(
        /*actSel*/2, 128, 120, 160,
        /*wSel*/2, /*coT*/128, /*multiSet*/0, 0, 9,
        /*outSel*/2, 128,
        1, 0, 1, 0, 160);

    // 6) BN stats for y2 from partials; final fuse: relu(bn(y2) + bn(ysc))
    combine_kernel<<<128, 256>>>(0, g2, b2, 3);
    final_kernel<<<19200, 256>>>(out);
}

// round 16
// speedup vs baseline: 1.3945x; 1.0434x over previous
#include <cuda_runtime.h>
#include <cuda_fp16.h>
#include <cstdint>
#include <cstddef>

#define BB   8
#define CIN  256
#define HWP  (120*160)   /* 19200 output plane size */
#define NSLOT 1200       /* partial-stats slots per channel (all convs) */

// ---------------- scratch (static device globals; no allocation) ----------------
// raw conv outputs now stored fp16 (BN stats come from fp32 register partials)
__device__ __half g_ybig[(size_t)BB * 256 * HWP]; // ch 0..127 conv1 raw, 128..255 shortcut raw
__device__ __half g_y11 [(size_t)BB * 128 * HWP];
__device__ __half g_y2  [(size_t)BB * 128 * HWP];
__device__ float g_ssA [256];   // (scale,shift) interleaved
__device__ float g_ssSC[256];
__device__ float g_ss11[256];
__device__ float g_ss2 [256];

// per-(channel, CTA-slot) partial sums for BN stats (written by conv epilogue)
__device__ float g_psum[256 * NSLOT];
__device__ float g_psq [256 * NSLOT];

// fp16 weights: [tap][co][ci]
__device__ __half g_wA [25 * 256 * 256];
__device__ __half g_w11[ 9 * 128 * 256];
__device__ __half g_w2 [ 9 * 128 * 128];

// fp16 activations, NHWC [b][pix][c]
__device__ __half g_xa [(size_t)BB *  4800 * 256];
__device__ __half g_cat[(size_t)BB * 19200 * 256];
__device__ __half g_a11[(size_t)BB * 19200 * 128];

__device__ __forceinline__ __half* pickBuf(int s) {
    return s == 0 ? g_ybig : (s == 1 ? g_y11 : g_y2);
}
__device__ __forceinline__ float* pickSS(int s) {
    return s == 0 ? g_ssA : (s == 1 ? g_ssSC : (s == 2 ? g_ss11 : g_ss2));
}
__device__ __forceinline__ __half* pickW(int s) {
    return s == 0 ? g_wA : (s == 1 ? g_w11 : g_w2);
}
__device__ __forceinline__ __half* pickAct(int s) {
    return s == 0 ? g_xa : (s == 1 ? g_cat : g_a11);
}

// ---------------- tap tables ----------------
__constant__ int c_dy[5][9] = {
    {-1,-1,-1, 0,0,0, 1,1,1},
    {-1,-1,-1, 0,0,0, 1,1,1},
    {-1,-1, 0,0, 1,1, 0,0,0},
    { 0, 0, 0, 1,1,1, 0,0,0},
    { 0, 0, 1, 1, 0,0,0,0,0},
};
__constant__ int c_dx[5][9] = {
    {-1,0,1, -1,0,1, -1,0,1},
    {-1,0,1, -1,0,1, -1,0,1},
    { 0,1, 0,1, 0,1, 0,0,0},
    {-1,0,1, -1,0,1, 0,0,0},
    { 0,1, 0,1, 0,0,0,0,0},
};
__constant__ int c_wi[5][9] = {
    {0,1,2, 3,4,5, 6,7,8},
    {0,2,4, 10,12,14, 20,22,24},
    {1,3, 11,13, 21,23, 0,0,0},
    {5,7,9, 15,17,19, 0,0,0},
    {6,8, 16,18, 0,0,0,0,0},
};
__constant__ int c_cntz[4] = {9, 6, 6, 4};
__constant__ int c_pyz [4] = {0, 0, 1, 1};
__constant__ int c_pxz [4] = {0, 1, 0, 1};

// ---------------- PTX helpers (sm_80+ baseline — compiles at sm_100) ----------------
__device__ __forceinline__ uint32_t smem_u32(const void* p) {
    uint32_t a;
    asm("{ .reg .u64 t; cvta.to.shared.u64 t, %1; cvt.u32.u64 %0, t; }" : "=r"(a) : "l"(p));
    return a;
}
__device__ __forceinline__ void ldsm_x4(uint32_t* r, uint32_t addr) {
    asm volatile("ldmatrix.sync.aligned.m8n8.x4.shared.b16 {%0,%1,%2,%3}, [%4];"
                 : "=r"(r[0]), "=r"(r[1]), "=r"(r[2]), "=r"(r[3]) : "r"(addr));
}
__device__ __forceinline__ void mma_f16(float* d, const uint32_t* a, const uint32_t* b) {
    asm volatile("mma.sync.aligned.m16n8k16.row.col.f32.f16.f16.f32 "
                 "{%0,%1,%2,%3},{%4,%5,%6,%7},{%8,%9},{%0,%1,%2,%3};"
                 : "+f"(d[0]), "+f"(d[1]), "+f"(d[2]), "+f"(d[3])
                 : "r"(a[0]), "r"(a[1]), "r"(a[2]), "r"(a[3]), "r"(b[0]), "r"(b[1]));
}
__device__ __forceinline__ void cp16(uint32_t dst, const void* src, uint32_t sz) {
    asm volatile("cp.async.cg.shared.global [%0], [%1], 16, %2;"
                 :: "r"(dst), "l"(src), "r"(sz) : "memory");
}
__device__ __forceinline__ void cp_commit() {
    asm volatile("cp.async.commit_group;" ::: "memory");
}
__device__ __forceinline__ void cp_wait1() {
    asm volatile("cp.async.wait_group 1;" ::: "memory");
}

// ---------------- SMEM layout: header + 3 pipeline stages (32KB each) ----------------
#define OFF_SB    0                    /* int[128] */
#define OFF_SY    512
#define OFF_SX    1024
#define OFF_STAGE 2048
#define STG_A     0                    /* 128co x 64ci fp16 = 16KB */
#define STG_B     16384                /* 128sp x 64ci fp16 = 16KB */
#define STAGE_BYTES 32768
#define NSTAGE    3
#define SMEM_BYTES (OFF_STAGE + NSTAGE * STAGE_BYTES)   /* 100352 -> 2 CTAs/SM */

// ---------------------------------------------------------------------------
// Weight prep: fp32 [co][ci][taps] -> fp16 [tap][co][ci].
// ---------------------------------------------------------------------------
__global__ void prep_kernel(const float* __restrict__ s0, const float* __restrict__ s1,
                            int coT, int ciT, int taps, int sel)
{
    const int idx = blockIdx.x * 256 + threadIdx.x;
    const int total = taps * coT * ciT;
    if (idx >= total) return;
    const int ci = idx % ciT;
    const int co = (idx / ciT) % coT;
    const int tap = idx / (ciT * coT);
    const float* s = s0;
    int c = co;
    if (s1 != nullptr && co >= 128) { s = s1; c = co - 128; }
    const float v = s[((size_t)c * ciT + ci) * taps + tap];
    pickW(sel)[idx] = __float2half_rn(v);
}

// ---------------------------------------------------------------------------
// Activation prep -> fp16 NHWC. Channel c < split: read fp16 scratch buffer
// (bufSel) with fused BN+ReLU. c >= split: read external fp32 (inB).
// Tile = 64 pixels x 64 channels with smem transpose.
// ---------------------------------------------------------------------------
__global__ __launch_bounds__(256)
void actprep_kernel(int bufSel, const float* __restrict__ inB,
                    int strA, int strB, int split, int C, int HW,
                    int ssSel, int dstSel)
{
    __shared__ __half s_t[64][72];
    const int tid = threadIdx.x;
    const int pix0 = blockIdx.x * 64;
    const int c0   = blockIdx.y * 64;
    const int b    = blockIdx.z;
    const __half* inA = pickBuf(bufSel);
    const float* ss  = pickSS(ssSel);
    __half* dst = pickAct(dstSel);

    const int cSub = tid >> 6, pixL = tid & 63;
#pragma unroll 4
    for (int ci = 0; ci < 16; ci++) {
        const int cl = ci * 4 + cSub;
        const int c = c0 + cl;
        float v;
        if (c < split) {
            v = __half2float(inA[((size_t)(b * strA + c)) * HW + pix0 + pixL]);
            v = fmaxf(fmaf(v, ss[2 * c], ss[2 * c + 1]), 0.f);
        } else {
            v = inB[((size_t)(b * strB + (c - split))) * HW + pix0 + pixL];
        }
        s_t[pixL][cl] = __float2half_rn(v);
    }
    __syncthreads();
    const int chunk = tid & 7, pL0 = tid >> 3;
#pragma unroll
    for (int h = 0; h < 2; h++) {
        const int pL = pL0 + h * 32;
        const uint4 vh = *(const uint4*)&s_t[pL][chunk * 8];
        const size_t doff = (size_t)(b * HW + pix0 + pL) * C + c0 + chunk * 8;
        *(uint4*)(dst + doff) = vh;
    }
}

// ---------------------------------------------------------------------------
// conv-as-tap-GEMM via mma.sync fp16 (single pass, fp32 accum).
// D[128 co][128 sp] per CTA, 8 warps 4(M)x2(N). 3-stage cp.async pipeline
// (depth-2 prefetch), one barrier per iteration, 2 CTAs/SM.
// A fragments double-buffered across k-groups; B within a k-group.
// Output written fp16 (half2-packed when oxMul==1).
// ---------------------------------------------------------------------------
__global__ __launch_bounds__(256, 2)
void conv_mma_kernel(
    int actSel, int C, int sH, int sW,
    int wSel, int coT,
    int multiSet, int tapSet, int tapCount,
    int outSel, int outBStride,
    int oyMul, int oyAdd, int oxMul, int oxAdd,
    int outW)
{
    extern __shared__ __align__(128) char smem[];
    const uint32_t sb = smem_u32(smem);
    int* s_bt = (int*)(smem + OFF_SB);
    int* s_yt = (int*)(smem + OFF_SY);
    int* s_xt = (int*)(smem + OFF_SX);

    const int tid = threadIdx.x;
    const int lane = tid & 31, wid = tid >> 5;
    const int wm = wid >> 1, wn = wid & 1;
    const int inHW = sH * sW;
    const int outHW = HWP;
    const int chanOff = blockIdx.y * 128;

    int tapSetL = tapSet, tapCountL = tapCount, oyAddL = oyAdd, oxAddL = oxAdd;
    if (multiSet) {
        const int z = blockIdx.z;
        tapSetL = z + 1;
        tapCountL = c_cntz[z];
        oyAddL = c_pyz[z];
        oxAddL = c_pxz[z];
    }
    const int slot = blockIdx.z * gridDim.x + blockIdx.x;   // 0..1199

    __half* outP = pickBuf(outSel);
    const __half* act = pickAct(actSel);
    const __half* wgt = pickW(wSel);

    if (tid < 128) {
        const int s = blockIdx.x * 128 + tid;
        const int b = s / inHW; const int r = s - b * inHW;
        const int y = r / sW;
        s_bt[tid] = b; s_yt[tid] = y; s_xt[tid] = r - y * sW;
    }
    __syncthreads();

    // staging mapping: 2 threads per row, 4 x 16B chunks each (A and B alike)
    const int rowS = tid >> 1, partS = tid & 1;
    const int bS = s_bt[rowS], yS = s_yt[rowS], xS = s_xt[rowS];
    const uint32_t bDst0 = sb + OFF_STAGE + STG_B + rowS * 128;
    const uint32_t aDst0 = sb + OFF_STAGE + STG_A + rowS * 128;
    const int swzS = rowS & 7;
    const size_t wRowBase = (size_t)(chanOff + rowS) * C;

    float acc[2][8][4];
#pragma unroll
    for (int i = 0; i < 2; i++)
#pragma unroll
        for (int j = 0; j < 8; j++)
#pragma unroll
            for (int k = 0; k < 4; k++) acc[i][j][k] = 0.f;

    // ldmatrix lane addressing (XOR swizzle on 128B rows)
    const int sx = lane & 7;
    const uint32_t aRowBase = (uint32_t)(wm * 32 + (lane & 15)) * 128;
    const uint32_t bRowBase = (uint32_t)(wn * 64 + (lane & 7) + ((lane >> 4) << 3)) * 128;
    const int ka0 = lane >> 4;
    const int kb0 = (lane >> 3) & 1;

    const int nIter = (C >> 6) * tapCountL;

    // ---- staging issue for iteration `it` into stage buffer `s` (0..2) ----
    auto stage = [&](int it, int s) {
        const int cbi = it / tapCountL;
        const int t   = it - cbi * tapCountL;
        const int cb  = cbi << 6;
        const int dy = c_dy[tapSetL][t], dx = c_dx[tapSetL][t], wi = c_wi[tapSetL][t];
        const uint32_t sOff = (uint32_t)s * STAGE_BYTES;
        // B: fp16 activation row for pixel rowS shifted by tap
        {
            const int yy = yS + dy, xx = xS + dx;
            const bool inb = ((unsigned)yy < (unsigned)sH) && ((unsigned)xx < (unsigned)sW);
            const __half* src = inb
                ? act + (size_t)(bS * inHW + yy * sW + xx) * C + cb
                : act;
            const uint32_t sz = inb ? 16u : 0u;
            const uint32_t d = bDst0 + sOff;
#pragma unroll
            for (int j = 0; j < 4; j++) {
                const int c8 = partS * 4 + j;
                cp16(d + ((c8 ^ swzS) << 4), src + c8 * 8, sz);
            }
        }
        // A: weight row (co = rowS) for this tap
        {
            const __half* src = wgt + (size_t)wi * coT * C + wRowBase + cb;
            const uint32_t d = aDst0 + sOff;
#pragma unroll
            for (int j = 0; j < 4; j++) {
                const int c8 = partS * 4 + j;
                cp16(d + ((c8 ^ swzS) << 4), src + c8 * 8, 16u);
            }
        }
    };

    // prologue: stage iters 0 and 1 (nIter >= 16 always)
    stage(0, 0); cp_commit();
    stage(1, 1); cp_commit();

    int st = 0;          // it % 3
    int st2 = 2;         // (it+2) % 3
    for (int it = 0; it < nIter; it++) {
        cp_wait1();          // group `it` complete (group it+1 still in flight)
        __syncthreads();     // data visible; all warps done with MMA(it-1)

        // depth-2 prefetch into buffer (it+2)%3 (last read by MMA(it-1))
        if (it + 2 < nIter) stage(it + 2, st2);
        cp_commit();         // possibly-empty group keeps the count uniform

        const uint32_t stBase = sb + OFF_STAGE + (uint32_t)st * STAGE_BYTES;
        const uint32_t Abase = stBase + STG_A;
        const uint32_t Bbase = stBase + STG_B;

        // A fragments double-buffered across k-groups
        uint32_t aA[2][4], aB[2][4];
        {
            const uint32_t aOff0 = (uint32_t)((ka0 ^ sx) << 4);
            ldsm_x4(aA[0], Abase + aRowBase + aOff0);
            ldsm_x4(aB[0], Abase + aRowBase + 16 * 128 + aOff0);
        }
#pragma unroll
        for (int k = 0; k < 4; k++) {
            const int cur = k & 1, nxt = cur ^ 1;
            if (k < 3) {
                const uint32_t aOffN = (uint32_t)(((ka0 + 2 * (k + 1)) ^ sx) << 4);
                ldsm_x4(aA[nxt], Abase + aRowBase + aOffN);
                ldsm_x4(aB[nxt], Abase + aRowBase + 16 * 128 + aOffN);
            }
            const uint32_t bOff = (uint32_t)(((kb0 + 2 * k) ^ sx) << 4);
            uint32_t bb[2][4];
            ldsm_x4(bb[0], Bbase + bRowBase + bOff);
#pragma unroll
            for (int tt = 0; tt < 4; tt++) {
                if (tt < 3)
                    ldsm_x4(bb[(tt + 1) & 1], Bbase + bRowBase + (tt + 1) * 2048 + bOff);
                const uint32_t* b = bb[tt & 1];
                mma_f16(acc[0][tt*2  ], aA[cur], b);
                mma_f16(acc[0][tt*2+1], aA[cur], b + 2);
                mma_f16(acc[1][tt*2  ], aB[cur], b);
                mma_f16(acc[1][tt*2+1], aB[cur], b + 2);
            }
        }
        st  = (st  == 2) ? 0 : st  + 1;
        st2 = (st2 == 2) ? 0 : st2 + 1;
    }

    // ---- epilogue: registers -> global (fp16 NCHW scratch) ----
    uint32_t off[16];
#pragma unroll
    for (int i = 0; i < 16; i++) {
        const int nf = i >> 1, e = i & 1;
        const int spi = wn * 64 + nf * 8 + (lane & 3) * 2 + e;
        const int b = s_bt[spi];
        const int oy = s_yt[spi] * oyMul + oyAddL;
        const int ox = s_xt[spi] * oxMul + oxAddL;
        off[i] = (uint32_t)(b * outBStride) * (uint32_t)outHW
               + (uint32_t)(oy * outW + ox);
    }
    const int coBase = chanOff + wm * 32 + (lane >> 2);
    if (oxMul == 1) {
        // adjacent e-pairs are contiguous pixels -> packed half2 stores
#pragma unroll
        for (int mi = 0; mi < 2; mi++) {
            const size_t cOff0 = (size_t)(coBase + mi * 16) * outHW;
            const size_t cOff8 = cOff0 + (size_t)8 * outHW;
#pragma unroll
            for (int nf = 0; nf < 8; nf++) {
                const __half2 v0 = __floats2half2_rn(acc[mi][nf][0], acc[mi][nf][1]);
                const __half2 v1 = __floats2half2_rn(acc[mi][nf][2], acc[mi][nf][3]);
                *(__half2*)(outP + cOff0 + off[nf*2]) = v0;
                *(__half2*)(outP + cOff8 + off[nf*2]) = v1;
            }
        }
    } else {
#pragma unroll
        for (int mi = 0; mi < 2; mi++) {
            const size_t cOff0 = (size_t)(coBase + mi * 16) * outHW;
            const size_t cOff8 = cOff0 + (size_t)8 * outHW;
#pragma unroll
            for (int nf = 0; nf < 8; nf++) {
                outP[cOff0 + off[nf*2  ]] = __float2half_rn(acc[mi][nf][0]);
                outP[cOff0 + off[nf*2+1]] = __float2half_rn(acc[mi][nf][1]);
                outP[cOff8 + off[nf*2  ]] = __float2half_rn(acc[mi][nf][2]);
                outP[cOff8 + off[nf*2+1]] = __float2half_rn(acc[mi][nf][3]);
            }
        }
    }

    // ---- deterministic per-(co, CTA) BN partials: sum & sumsq (fp32 exact) ----
    float ps[4], pq[4];
#pragma unroll
    for (int mi = 0; mi < 2; mi++)
#pragma unroll
        for (int h = 0; h < 2; h++) {
            float s = 0.f, q = 0.f;
#pragma unroll
            for (int nf = 0; nf < 8; nf++)
#pragma unroll
                for (int e = 0; e < 2; e++) {
                    const float v = acc[mi][nf][h * 2 + e];
                    s += v; q += v * v;
                }
            ps[mi * 2 + h] = s; pq[mi * 2 + h] = q;
        }
#pragma unroll
    for (int i = 0; i < 4; i++) {
        ps[i] += __shfl_xor_sync(0xffffffffu, ps[i], 1);
        ps[i] += __shfl_xor_sync(0xffffffffu, ps[i], 2);
        pq[i] += __shfl_xor_sync(0xffffffffu, pq[i], 1);
        pq[i] += __shfl_xor_sync(0xffffffffu, pq[i], 2);
    }
    __syncthreads();    // mainloop smem reads done; reuse stage 0 as scratch
    float* sred = (float*)(smem + OFF_STAGE);          // [2][128]
    float* qred = (float*)(smem + OFF_STAGE + 1024);   // [2][128]
    if ((lane & 3) == 0) {
        const int l4 = lane >> 2;
#pragma unroll
        for (int mi = 0; mi < 2; mi++)
#pragma unroll
            for (int h = 0; h < 2; h++) {
                const int col = wm * 32 + l4 + mi * 16 + h * 8;
                sred[wn * 128 + col] = ps[mi * 2 + h];
                qred[wn * 128 + col] = pq[mi * 2 + h];
            }
    }
    __syncthreads();
    if (tid < 128) {
        const float s = sred[tid] + sred[128 + tid];
        const float q = qred[tid] + qred[128 + tid];
        g_psum[(size_t)(chanOff + tid) * NSLOT + slot] = s;
        g_psq [(size_t)(chanOff + tid) * NSLOT + slot] = q;
    }
}

// ---------------------------------------------------------------------------
// Combine per-CTA partials -> (scale, shift). One block per channel.
// ---------------------------------------------------------------------------
__global__ void combine_kernel(int chanOff,
                               const float* __restrict__ gamma,
                               const float* __restrict__ beta,
                               int ssSel)
{
    float* ss = pickSS(ssSel);
    const int c = blockIdx.x;
    const int tid = threadIdx.x;
    const float* psp = g_psum + (size_t)(chanOff + c) * NSLOT;
    const float* pqp = g_psq  + (size_t)(chanOff + c) * NSLOT;
    float s = 0.f, q = 0.f;
    for (int i = tid; i < NSLOT; i += 256) { s += psp[i]; q += pqp[i]; }
    __shared__ float red[512];
    red[tid] = s; red[256 + tid] = q;
    __syncthreads();
    for (int off = 128; off > 0; off >>= 1) {
        if (tid < off) {
            red[tid]       += red[tid + off];
            red[256 + tid] += red[256 + tid + off];
        }
        __syncthreads();
    }
    if (tid == 0) {
        const float N = (float)(BB * HWP);
        float mean = red[0] / N;
        float var  = red[256] / N - mean * mean;
        float inv  = rsqrtf(var + 1e-5f);
        float scv  = gamma[c] * inv;
        ss[2 * c]     = scv;
        ss[2 * c + 1] = beta[c] - mean * scv;
    }
}

// out = relu(bn(y2) + bn(ysc)), reading fp16 scratch
__global__ void final_kernel(float* __restrict__ out)
{
    const int t  = blockIdx.x * 256 + threadIdx.x;
    const int p  = t % 4800;
    const int bc = t / 4800;
    const int b = bc >> 7, c = bc & 127;
    const float s2  = g_ss2[2 * c],  t2  = g_ss2[2 * c + 1];
    const float ssc = g_ssSC[2 * c], tsc = g_ssSC[2 * c + 1];
    const __half2* ap = (const __half2*)(g_y2   + (size_t)(b * 128 + c) * HWP) + 2 * p;
    const __half2* dp = (const __half2*)(g_ybig + (size_t)(b * 256 + 128 + c) * HWP) + 2 * p;
    const float2 a01 = __half22float2(ap[0]);
    const float2 a23 = __half22float2(ap[1]);
    const float2 d01 = __half22float2(dp[0]);
    const float2 d23 = __half22float2(dp[1]);
    float4 o;
    o.x = fmaxf(fmaf(a01.x, s2, t2) + fmaf(d01.x, ssc, tsc), 0.f);
    o.y = fmaxf(fmaf(a01.y, s2, t2) + fmaf(d01.y, ssc, tsc), 0.f);
    o.z = fmaxf(fmaf(a23.x, s2, t2) + fmaf(d23.x, ssc, tsc), 0.f);
    o.w = fmaxf(fmaf(a23.y, s2, t2) + fmaf(d23.y, ssc, tsc), 0.f);
    ((float4*)out)[t] = o;
}

// ---------------------------------------------------------------------------
extern "C" void kernel_launch(void* const* d_in, const int* in_sizes, int n_in,
                              void* d_out, int out_size)
{
    const float* x    = (const float*)d_in[0];
    const float* side = (const float*)d_in[1];
    const float* w1   = (const float*)d_in[2];
    const float* g1   = (const float*)d_in[3];
    const float* b1   = (const float*)d_in[4];
    const float* w11  = (const float*)d_in[5];
    const float* g11  = (const float*)d_in[6];
    const float* b11  = (const float*)d_in[7];
    const float* w2   = (const float*)d_in[8];
    const float* g2   = (const float*)d_in[9];
    const float* b2   = (const float*)d_in[10];
    const float* wsc  = (const float*)d_in[11];
    const float* gsc  = (const float*)d_in[12];
    const float* bsc  = (const float*)d_in[13];
    float* out = (float*)d_out;

    cudaFuncSetAttribute(conv_mma_kernel,
                         cudaFuncAttributeMaxDynamicSharedMemorySize, SMEM_BYTES);

    // 0) weights -> fp16 [tap][co][ci]
    prep_kernel<<<(25*256*256 + 255)/256, 256>>>(w1, wsc, 256, 256, 25, 0);
    prep_kernel<<<( 9*128*256 + 255)/256, 256>>>(w11, nullptr, 128, 256, 9, 1);
    prep_kernel<<<( 9*128*128 + 255)/256, 256>>>(w2,  nullptr, 128, 128, 9, 2);

    // 0b) x -> fp16 NHWC (pure external path: split=0, inB=x)
    {
        dim3 g(4800/64, 256/64, BB);
        actprep_kernel<<<g, 256>>>(0, x, 0, CIN, 0, 256, 4800, 0, 0);
    }

    // 1) sparse 5x5 conv, all 4 parity sets in ONE launch (z = set-1).
    {
        dim3 gA(300, 2, 4);
        conv_mma_kernel<<<gA, 256, SMEM_BYTES>>>(
            /*actSel*/0, 256, 60, 80,
            /*wSel*/0, /*coT*/256, /*multiSet*/1, 0, 0,
            /*outSel*/0, 256,
            2, 0, 2, 0, 160);
    }

    // 2) BN stats from conv partials (both halves)
    combine_kernel<<<128, 256>>>(0,   g1,  b1,  0);
    combine_kernel<<<128, 256>>>(128, gsc, bsc, 1);

    // 2b) concat input: bn+relu(y1) ch 0..127 (fp16 buf), side ch 128..255 -> fp16 NHWC
    {
        dim3 g(19200/64, 256/64, BB);
        actprep_kernel<<<g, 256>>>(0, side, 256, 128, 128, 256, 19200, 0, 1);
    }

    // 3) conv3x3 over concat -> y11 (fp16)
    dim3 g3(1200, 1, 1);
    conv_mma_kernel<<<g3, 256, SMEM_BYTES>>>(
        /*actSel*/1, 256, 120, 160,
        /*wSel*/1, /*coT*/128, /*multiSet*/0, 0, 9,
        /*outSel*/1, 128,
        1, 0, 1, 0, 160);

    // 4) BN stats on y11 from partials; a11 = relu(bn(y11)) -> fp16 NHWC
    combine_kernel<<<128, 256>>>(0, g11, b11, 2);
    {
        dim3 g(19200/64, 128/64, BB);
        actprep_kernel<<<g, 256>>>(1, nullptr, 128, 0, 128, 128, 19200, 2, 2);
    }

    // 5) conv3x3 (Cin=128) -> y2 (fp16)
    conv_mma_kernel<<<g3, 256, SMEM_BYTES>>>(
        /*actSel*/2, 128, 120, 160,
        /*wSel*/2, /*coT*/128, /*multiSet*/0, 0, 9,
        /*outSel*/2, 128,
        1, 0, 1, 0, 160);

    // 6) BN stats for y2 from partials; final fuse: relu(bn(y2) + bn(ysc))
    combine_kernel<<<128, 256>>>(0, g2, b2, 3);
    final_kernel<<<19200, 256>>>(out);
}

// round 17
// speedup vs baseline: 1.5112x; 1.0837x over previous
#include <cuda_runtime.h>
#include <cuda_fp16.h>
#include <cstdint>
#include <cstddef>

#define BB   8
#define CIN  256
#define HWP  (120*160)   /* 19200 output plane size */
#define NSLOT 1200       /* partial-stats slots per channel (all convs) */

// ---------------- scratch (static device globals; no allocation) ----------------
__device__ __half g_ybig[(size_t)BB * 256 * HWP]; // ch 0..127 conv1 raw, 128..255 shortcut raw
__device__ __half g_y11 [(size_t)BB * 128 * HWP];
__device__ __half g_y2  [(size_t)BB * 128 * HWP];
__device__ float g_ssA [256];   // (scale,shift) interleaved
__device__ float g_ssSC[256];
__device__ float g_ss11[256];
__device__ float g_ss2 [256];

// per-(channel, CTA-slot) partial sums for BN stats (written by conv epilogue)
__device__ float g_psum[256 * NSLOT];
__device__ float g_psq [256 * NSLOT];

// fp16 weights: [tap][co][ci]
__device__ __half g_wA [25 * 256 * 256];
__device__ __half g_w11[ 9 * 128 * 256];
__device__ __half g_w2 [ 9 * 128 * 128];

// fp16 activations, NHWC [b][pix][c]
__device__ __half g_xa [(size_t)BB *  4800 * 256];
__device__ __half g_cat[(size_t)BB * 19200 * 256];
__device__ __half g_a11[(size_t)BB * 19200 * 128];

__device__ __forceinline__ __half* pickBuf(int s) {
    return s == 0 ? g_ybig : (s == 1 ? g_y11 : g_y2);
}
__device__ __forceinline__ float* pickSS(int s) {
    return s == 0 ? g_ssA : (s == 1 ? g_ssSC : (s == 2 ? g_ss11 : g_ss2));
}
__device__ __forceinline__ __half* pickW(int s) {
    return s == 0 ? g_wA : (s == 1 ? g_w11 : g_w2);
}
__device__ __forceinline__ __half* pickAct(int s) {
    return s == 0 ? g_xa : (s == 1 ? g_cat : g_a11);
}

// ---------------- tap tables ----------------
__constant__ int c_dy[5][9] = {
    {-1,-1,-1, 0,0,0, 1,1,1},
    {-1,-1,-1, 0,0,0, 1,1,1},
    {-1,-1, 0,0, 1,1, 0,0,0},
    { 0, 0, 0, 1,1,1, 0,0,0},
    { 0, 0, 1, 1, 0,0,0,0,0},
};
__constant__ int c_dx[5][9] = {
    {-1,0,1, -1,0,1, -1,0,1},
    {-1,0,1, -1,0,1, -1,0,1},
    { 0,1, 0,1, 0,1, 0,0,0},
    {-1,0,1, -1,0,1, 0,0,0},
    { 0,1, 0,1, 0,0,0,0,0},
};
__constant__ int c_wi[5][9] = {
    {0,1,2, 3,4,5, 6,7,8},
    {0,2,4, 10,12,14, 20,22,24},
    {1,3, 11,13, 21,23, 0,0,0},
    {5,7,9, 15,17,19, 0,0,0},
    {6,8, 16,18, 0,0,0,0,0},
};
__constant__ int c_cntz[4] = {9, 6, 6, 4};
__constant__ int c_pyz [4] = {0, 0, 1, 1};
__constant__ int c_pxz [4] = {0, 1, 0, 1};

// ---------------- PTX helpers (sm_80+ baseline — compiles at sm_100) ----------------
__device__ __forceinline__ uint32_t smem_u32(const void* p) {
    uint32_t a;
    asm("{ .reg .u64 t; cvta.to.shared.u64 t, %1; cvt.u32.u64 %0, t; }" : "=r"(a) : "l"(p));
    return a;
}
__device__ __forceinline__ void ldsm_x4(uint32_t* r, uint32_t addr) {
    asm volatile("ldmatrix.sync.aligned.m8n8.x4.shared.b16 {%0,%1,%2,%3}, [%4];"
                 : "=r"(r[0]), "=r"(r[1]), "=r"(r[2]), "=r"(r[3]) : "r"(addr));
}
__device__ __forceinline__ void mma_f16(float* d, const uint32_t* a, const uint32_t* b) {
    asm volatile("mma.sync.aligned.m16n8k16.row.col.f32.f16.f16.f32 "
                 "{%0,%1,%2,%3},{%4,%5,%6,%7},{%8,%9},{%0,%1,%2,%3};"
                 : "+f"(d[0]), "+f"(d[1]), "+f"(d[2]), "+f"(d[3])
                 : "r"(a[0]), "r"(a[1]), "r"(a[2]), "r"(a[3]), "r"(b[0]), "r"(b[1]));
}
__device__ __forceinline__ void cp16(uint32_t dst, const void* src, uint32_t sz) {
    asm volatile("cp.async.cg.shared.global [%0], [%1], 16, %2;"
                 :: "r"(dst), "l"(src), "r"(sz) : "memory");
}
__device__ __forceinline__ void cp_commit() {
    asm volatile("cp.async.commit_group;" ::: "memory");
}
__device__ __forceinline__ void cp_wait1() {
    asm volatile("cp.async.wait_group 1;" ::: "memory");
}

// ---------------- SMEM layout: header + 3 pipeline stages (32KB each) ----------------
#define OFF_SB    0                    /* int[128] */
#define OFF_SY    512
#define OFF_SX    1024
#define OFF_STAGE 2048
#define STG_A     0                    /* 128co x 64ci fp16 = 16KB */
#define STG_B     16384                /* 128sp x 64ci fp16 = 16KB */
#define STAGE_BYTES 32768
#define NSTAGE    3
#define SMEM_BYTES (OFF_STAGE + NSTAGE * STAGE_BYTES)   /* 100352 -> 2 CTAs/SM */

// ---------------------------------------------------------------------------
// Weight prep: fp32 [co][ci][taps] -> fp16 [tap][co][ci].
// ---------------------------------------------------------------------------
__global__ void prep_kernel(const float* __restrict__ s0, const float* __restrict__ s1,
                            int coT, int ciT, int taps, int sel)
{
    const int idx = blockIdx.x * 256 + threadIdx.x;
    const int total = taps * coT * ciT;
    if (idx >= total) return;
    const int ci = idx % ciT;
    const int co = (idx / ciT) % coT;
    const int tap = idx / (ciT * coT);
    const float* s = s0;
    int c = co;
    if (s1 != nullptr && co >= 128) { s = s1; c = co - 128; }
    const float v = s[((size_t)c * ciT + ci) * taps + tap];
    pickW(sel)[idx] = __float2half_rn(v);
}

// ---------------------------------------------------------------------------
// Activation prep -> fp16 NHWC. Channel c < split: read fp16 scratch buffer
// (bufSel) with fused BN+ReLU. c >= split: read external fp32 (inB).
// Tile = 64 pixels x 64 channels with smem transpose.
// ---------------------------------------------------------------------------
__global__ __launch_bounds__(256)
void actprep_kernel(int bufSel, const float* __restrict__ inB,
                    int strA, int strB, int split, int C, int HW,
                    int ssSel, int dstSel)
{
    __shared__ __half s_t[64][72];
    const int tid = threadIdx.x;
    const int pix0 = blockIdx.x * 64;
    const int c0   = blockIdx.y * 64;
    const int b    = blockIdx.z;
    const __half* inA = pickBuf(bufSel);
    const float* ss  = pickSS(ssSel);
    __half* dst = pickAct(dstSel);

    const int cSub = tid >> 6, pixL = tid & 63;
#pragma unroll 4
    for (int ci = 0; ci < 16; ci++) {
        const int cl = ci * 4 + cSub;
        const int c = c0 + cl;
        float v;
        if (c < split) {
            v = __half2float(inA[((size_t)(b * strA + c)) * HW + pix0 + pixL]);
            v = fmaxf(fmaf(v, ss[2 * c], ss[2 * c + 1]), 0.f);
        } else {
            v = inB[((size_t)(b * strB + (c - split))) * HW + pix0 + pixL];
        }
        s_t[pixL][cl] = __float2half_rn(v);
    }
    __syncthreads();
    const int chunk = tid & 7, pL0 = tid >> 3;
#pragma unroll
    for (int h = 0; h < 2; h++) {
        const int pL = pL0 + h * 32;
        const uint4 vh = *(const uint4*)&s_t[pL][chunk * 8];
        const size_t doff = (size_t)(b * HW + pix0 + pL) * C + c0 + chunk * 8;
        *(uint4*)(dst + doff) = vh;
    }
}

// ---------------------------------------------------------------------------
// conv-as-tap-GEMM via mma.sync fp16 (single pass, fp32 accum).
// D[128 co][128 sp] per CTA, 8 warps 4(M)x2(N). 3-stage cp.async pipeline
// (depth-2 prefetch), one barrier per iteration, 2 CTAs/SM.
// MMA issued FIRST each iteration; next-stage cp.async issued after (tensor
// pipe starts immediately after the barrier).
// ---------------------------------------------------------------------------
__global__ __launch_bounds__(256, 2)
void conv_mma_kernel(
    int actSel, int C, int sH, int sW,
    int wSel, int coT,
    int multiSet, int tapSet, int tapCount,
    int outSel, int outBStride,
    int oyMul, int oyAdd, int oxMul, int oxAdd,
    int outW)
{
    extern __shared__ __align__(128) char smem[];
    const uint32_t sb = smem_u32(smem);
    int* s_bt = (int*)(smem + OFF_SB);
    int* s_yt = (int*)(smem + OFF_SY);
    int* s_xt = (int*)(smem + OFF_SX);

    const int tid = threadIdx.x;
    const int lane = tid & 31, wid = tid >> 5;
    const int wm = wid >> 1, wn = wid & 1;
    const int inHW = sH * sW;
    const int outHW = HWP;
    const int chanOff = blockIdx.y * 128;

    int tapSetL = tapSet, tapCountL = tapCount, oyAddL = oyAdd, oxAddL = oxAdd;
    if (multiSet) {
        const int z = blockIdx.z;
        tapSetL = z + 1;
        tapCountL = c_cntz[z];
        oyAddL = c_pyz[z];
        oxAddL = c_pxz[z];
    }
    const int slot = blockIdx.z * gridDim.x + blockIdx.x;   // 0..1199

    __half* outP = pickBuf(outSel);
    const __half* act = pickAct(actSel);
    const __half* wgt = pickW(wSel);

    if (tid < 128) {
        const int s = blockIdx.x * 128 + tid;
        const int b = s / inHW; const int r = s - b * inHW;
        const int y = r / sW;
        s_bt[tid] = b; s_yt[tid] = y; s_xt[tid] = r - y * sW;
    }
    __syncthreads();

    // staging mapping: 2 threads per row, 4 x 16B chunks each (A and B alike)
    const int rowS = tid >> 1, partS = tid & 1;
    const int bS = s_bt[rowS], yS = s_yt[rowS], xS = s_xt[rowS];
    const uint32_t bDst0 = sb + OFF_STAGE + STG_B + rowS * 128;
    const uint32_t aDst0 = sb + OFF_STAGE + STG_A + rowS * 128;
    const int swzS = rowS & 7;
    const size_t wRowBase = (size_t)(chanOff + rowS) * C;

    float acc[2][8][4];
#pragma unroll
    for (int i = 0; i < 2; i++)
#pragma unroll
        for (int j = 0; j < 8; j++)
#pragma unroll
            for (int k = 0; k < 4; k++) acc[i][j][k] = 0.f;

    // ldmatrix lane addressing (XOR swizzle on 128B rows)
    const int sx = lane & 7;
    const uint32_t aRowBase = (uint32_t)(wm * 32 + (lane & 15)) * 128;
    const uint32_t bRowBase = (uint32_t)(wn * 64 + (lane & 7) + ((lane >> 4) << 3)) * 128;
    const int ka0 = lane >> 4;
    const int kb0 = (lane >> 3) & 1;

    const int nIter = (C >> 6) * tapCountL;

    // ---- staging issue for iteration `it` into stage buffer `s` (0..2) ----
    auto stage = [&](int it, int s) {
        const int cbi = it / tapCountL;
        const int t   = it - cbi * tapCountL;
        const int cb  = cbi << 6;
        const int dy = c_dy[tapSetL][t], dx = c_dx[tapSetL][t], wi = c_wi[tapSetL][t];
        const uint32_t sOff = (uint32_t)s * STAGE_BYTES;
        // B: fp16 activation row for pixel rowS shifted by tap
        {
            const int yy = yS + dy, xx = xS + dx;
            const bool inb = ((unsigned)yy < (unsigned)sH) && ((unsigned)xx < (unsigned)sW);
            const __half* src = inb
                ? act + (size_t)(bS * inHW + yy * sW + xx) * C + cb
                : act;
            const uint32_t sz = inb ? 16u : 0u;
            const uint32_t d = bDst0 + sOff;
#pragma unroll
            for (int j = 0; j < 4; j++) {
                const int c8 = partS * 4 + j;
                cp16(d + ((c8 ^ swzS) << 4), src + c8 * 8, sz);
            }
        }
        // A: weight row (co = rowS) for this tap
        {
            const __half* src = wgt + (size_t)wi * coT * C + wRowBase + cb;
            const uint32_t d = aDst0 + sOff;
#pragma unroll
            for (int j = 0; j < 4; j++) {
                const int c8 = partS * 4 + j;
                cp16(d + ((c8 ^ swzS) << 4), src + c8 * 8, 16u);
            }
        }
    };

    // prologue: stage iters 0 and 1 (nIter >= 16 always)
    stage(0, 0); cp_commit();
    stage(1, 1); cp_commit();

    int st = 0;          // it % 3
    int st2 = 2;         // (it+2) % 3
    for (int it = 0; it < nIter; it++) {
        cp_wait1();          // group `it` complete (group it+1 still in flight)
        __syncthreads();     // data visible; all warps done with MMA(it-1)

        const uint32_t stBase = sb + OFF_STAGE + (uint32_t)st * STAGE_BYTES;
        const uint32_t Abase = stBase + STG_A;
        const uint32_t Bbase = stBase + STG_B;

        // ---- MMA first: tensor pipe starts immediately after barrier ----
        uint32_t aA[2][4], aB[2][4];
        {
            const uint32_t aOff0 = (uint32_t)((ka0 ^ sx) << 4);
            ldsm_x4(aA[0], Abase + aRowBase + aOff0);
            ldsm_x4(aB[0], Abase + aRowBase + 16 * 128 + aOff0);
        }
#pragma unroll
        for (int k = 0; k < 4; k++) {
            const int cur = k & 1, nxt = cur ^ 1;
            if (k < 3) {
                const uint32_t aOffN = (uint32_t)(((ka0 + 2 * (k + 1)) ^ sx) << 4);
                ldsm_x4(aA[nxt], Abase + aRowBase + aOffN);
                ldsm_x4(aB[nxt], Abase + aRowBase + 16 * 128 + aOffN);
            }
            const uint32_t bOff = (uint32_t)(((kb0 + 2 * k) ^ sx) << 4);
            uint32_t bb[2][4];
            ldsm_x4(bb[0], Bbase + bRowBase + bOff);
#pragma unroll
            for (int tt = 0; tt < 4; tt++) {
                if (tt < 3)
                    ldsm_x4(bb[(tt + 1) & 1], Bbase + bRowBase + (tt + 1) * 2048 + bOff);
                const uint32_t* b = bb[tt & 1];
                mma_f16(acc[0][tt*2  ], aA[cur], b);
                mma_f16(acc[0][tt*2+1], aA[cur], b + 2);
                mma_f16(acc[1][tt*2  ], aB[cur], b);
                mma_f16(acc[1][tt*2+1], aB[cur], b + 2);
            }
        }

        // ---- then prefetch iter it+2 into buffer (it+2)%3 ----
        // (safe: barrier at top of this iter guaranteed MMA(it-1), the last
        //  reader of that buffer, is complete CTA-wide)
        if (it + 2 < nIter) stage(it + 2, st2);
        cp_commit();         // possibly-empty group keeps the count uniform

        st  = (st  == 2) ? 0 : st  + 1;
        st2 = (st2 == 2) ? 0 : st2 + 1;
    }

    // ---- epilogue: registers -> global (fp16 NCHW scratch) ----
    uint32_t off[16];
#pragma unroll
    for (int i = 0; i < 16; i++) {
        const int nf = i >> 1, e = i & 1;
        const int spi = wn * 64 + nf * 8 + (lane & 3) * 2 + e;
        const int b = s_bt[spi];
        const int oy = s_yt[spi] * oyMul + oyAddL;
        const int ox = s_xt[spi] * oxMul + oxAddL;
        off[i] = (uint32_t)(b * outBStride) * (uint32_t)outHW
               + (uint32_t)(oy * outW + ox);
    }
    const int coBase = chanOff + wm * 32 + (lane >> 2);
    if (oxMul == 1) {
#pragma unroll
        for (int mi = 0; mi < 2; mi++) {
            const size_t cOff0 = (size_t)(coBase + mi * 16) * outHW;
            const size_t cOff8 = cOff0 + (size_t)8 * outHW;
#pragma unroll
            for (int nf = 0; nf < 8; nf++) {
                const __half2 v0 = __floats2half2_rn(acc[mi][nf][0], acc[mi][nf][1]);
                const __half2 v1 = __floats2half2_rn(acc[mi][nf][2], acc[mi][nf][3]);
                *(__half2*)(outP + cOff0 + off[nf*2]) = v0;
                *(__half2*)(outP + cOff8 + off[nf*2]) = v1;
            }
        }
    } else {
#pragma unroll
        for (int mi = 0; mi < 2; mi++) {
            const size_t cOff0 = (size_t)(coBase + mi * 16) * outHW;
            const size_t cOff8 = cOff0 + (size_t)8 * outHW;
#pragma unroll
            for (int nf = 0; nf < 8; nf++) {
                outP[cOff0 + off[nf*2  ]] = __float2half_rn(acc[mi][nf][0]);
                outP[cOff0 + off[nf*2+1]] = __float2half_rn(acc[mi][nf][1]);
                outP[cOff8 + off[nf*2  ]] = __float2half_rn(acc[mi][nf][2]);
                outP[cOff8 + off[nf*2+1]] = __float2half_rn(acc[mi][nf][3]);
            }
        }
    }

    // ---- deterministic per-(co, CTA) BN partials: sum & sumsq (fp32 exact) ----
    float ps[4], pq[4];
#pragma unroll
    for (int mi = 0; mi < 2; mi++)
#pragma unroll
        for (int h = 0; h < 2; h++) {
            float s = 0.f, q = 0.f;
#pragma unroll
            for (int nf = 0; nf < 8; nf++)
#pragma unroll
                for (int e = 0; e < 2; e++) {
                    const float v = acc[mi][nf][h * 2 + e];
                    s += v; q += v * v;
                }
            ps[mi * 2 + h] = s; pq[mi * 2 + h] = q;
        }
#pragma unroll
    for (int i = 0; i < 4; i++) {
        ps[i] += __shfl_xor_sync(0xffffffffu, ps[i], 1);
        ps[i] += __shfl_xor_sync(0xffffffffu, ps[i], 2);
        pq[i] += __shfl_xor_sync(0xffffffffu, pq[i], 1);
        pq[i] += __shfl_xor_sync(0xffffffffu, pq[i], 2);
    }
    __syncthreads();    // mainloop smem reads done; reuse stage 0 as scratch
    float* sred = (float*)(smem + OFF_STAGE);          // [2][128]
    float* qred = (float*)(smem + OFF_STAGE + 1024);   // [2][128]
    if ((lane & 3) == 0) {
        const int l4 = lane >> 2;
#pragma unroll
        for (int mi = 0; mi < 2; mi++)
#pragma unroll
            for (int h = 0; h < 2; h++) {
                const int col = wm * 32 + l4 + mi * 16 + h * 8;
                sred[wn * 128 + col] = ps[mi * 2 + h];
                qred[wn * 128 + col] = pq[mi * 2 + h];
            }
    }
    __syncthreads();
    if (tid < 128) {
        const float s = sred[tid] + sred[128 + tid];
        const float q = qred[tid] + qred[128 + tid];
        g_psum[(size_t)(chanOff + tid) * NSLOT + slot] = s;
        g_psq [(size_t)(chanOff + tid) * NSLOT + slot] = q;
    }
}

// ---------------------------------------------------------------------------
// Combine per-CTA partials -> (scale, shift). One block per channel.
// dual=1: 256 blocks, block>=128 uses (gamma1,beta1,ssSel1) with chanOff 128.
// ---------------------------------------------------------------------------
__global__ void combine_kernel(int dual,
                               const float* __restrict__ gamma0,
                               const float* __restrict__ beta0,
                               int ssSel0,
                               const float* __restrict__ gamma1,
                               const float* __restrict__ beta1,
                               int ssSel1)
{
    int c = blockIdx.x;
    int chanOff = 0;
    const float* gamma = gamma0;
    const float* beta  = beta0;
    int ssSel = ssSel0;
    if (dual && c >= 128) {
        c -= 128; chanOff = 128; gamma = gamma1; beta = beta1; ssSel = ssSel1;
    }
    float* ss = pickSS(ssSel);
    const int tid = threadIdx.x;
    const float* psp = g_psum + (size_t)(chanOff + c) * NSLOT;
    const float* pqp = g_psq  + (size_t)(chanOff + c) * NSLOT;
    float s = 0.f, q = 0.f;
    for (int i = tid; i < NSLOT; i += 256) { s += psp[i]; q += pqp[i]; }
    __shared__ float red[512];
    red[tid] = s; red[256 + tid] = q;
    __syncthreads();
    for (int off = 128; off > 0; off >>= 1) {
        if (tid < off) {
            red[tid]       += red[tid + off];
            red[256 + tid] += red[256 + tid + off];
        }
        __syncthreads();
    }
    if (tid == 0) {
        const float N = (float)(BB * HWP);
        float mean = red[0] / N;
        float var  = red[256] / N - mean * mean;
        float inv  = rsqrtf(var + 1e-5f);
        float scv  = gamma[c] * inv;
        ss[2 * c]     = scv;
        ss[2 * c + 1] = beta[c] - mean * scv;
    }
}

// out = relu(bn(y2) + bn(ysc)), reading fp16 scratch
__global__ void final_kernel(float* __restrict__ out)
{
    const int t  = blockIdx.x * 256 + threadIdx.x;
    const int p  = t % 4800;
    const int bc = t / 4800;
    const int b = bc >> 7, c = bc & 127;
    const float s2  = g_ss2[2 * c],  t2  = g_ss2[2 * c + 1];
    const float ssc = g_ssSC[2 * c], tsc = g_ssSC[2 * c + 1];
    const __half2* ap = (const __half2*)(g_y2   + (size_t)(b * 128 + c) * HWP) + 2 * p;
    const __half2* dp = (const __half2*)(g_ybig + (size_t)(b * 256 + 128 + c) * HWP) + 2 * p;
    const float2 a01 = __half22float2(ap[0]);
    const float2 a23 = __half22float2(ap[1]);
    const float2 d01 = __half22float2(dp[0]);
    const float2 d23 = __half22float2(dp[1]);
    float4 o;
    o.x = fmaxf(fmaf(a01.x, s2, t2) + fmaf(d01.x, ssc, tsc), 0.f);
    o.y = fmaxf(fmaf(a01.y, s2, t2) + fmaf(d01.y, ssc, tsc), 0.f);
    o.z = fmaxf(fmaf(a23.x, s2, t2) + fmaf(d23.x, ssc, tsc), 0.f);
    o.w = fmaxf(fmaf(a23.y, s2, t2) + fmaf(d23.y, ssc, tsc), 0.f);
    ((float4*)out)[t] = o;
}

// ---------------------------------------------------------------------------
extern "C" void kernel_launch(void* const* d_in, const int* in_sizes, int n_in,
                              void* d_out, int out_size)
{
    const float* x    = (const float*)d_in[0];
    const float* side = (const float*)d_in[1];
    const float* w1   = (const float*)d_in[2];
    const float* g1   = (const float*)d_in[3];
    const float* b1   = (const float*)d_in[4];
    const float* w11  = (const float*)d_in[5];
    const float* g11  = (const float*)d_in[6];
    const float* b11  = (const float*)d_in[7];
    const float* w2   = (const float*)d_in[8];
    const float* g2   = (const float*)d_in[9];
    const float* b2   = (const float*)d_in[10];
    const float* wsc  = (const float*)d_in[11];
    const float* gsc  = (const float*)d_in[12];
    const float* bsc  = (const float*)d_in[13];
    float* out = (float*)d_out;

    cudaFuncSetAttribute(conv_mma_kernel,
                         cudaFuncAttributeMaxDynamicSharedMemorySize, SMEM_BYTES);

    // 0) weights -> fp16 [tap][co][ci]
    prep_kernel<<<(25*256*256 + 255)/256, 256>>>(w1, wsc, 256, 256, 25, 0);
    prep_kernel<<<( 9*128*256 + 255)/256, 256>>>(w11, nullptr, 128, 256, 9, 1);
    prep_kernel<<<( 9*128*128 + 255)/256, 256>>>(w2,  nullptr, 128, 128, 9, 2);

    // 0b) x -> fp16 NHWC (pure external path: split=0, inB=x)
    {
        dim3 g(4800/64, 256/64, BB);
        actprep_kernel<<<g, 256>>>(0, x, 0, CIN, 0, 256, 4800, 0, 0);
    }

    // 1) sparse 5x5 conv, all 4 parity sets in ONE launch (z = set-1).
    {
        dim3 gA(300, 2, 4);
        conv_mma_kernel<<<gA, 256, SMEM_BYTES>>>(
            /*actSel*/0, 256, 60, 80,
            /*wSel*/0, /*coT*/256, /*multiSet*/1, 0, 0,
            /*outSel*/0, 256,
            2, 0, 2, 0, 160);
    }

    // 2) BN stats from conv partials — both halves in ONE launch
    combine_kernel<<<256, 256>>>(1, g1, b1, 0, gsc, bsc, 1);

    // 2b) concat input: bn+relu(y1) ch 0..127 (fp16 buf), side ch 128..255 -> fp16 NHWC
    {
        dim3 g(19200/64, 256/64, BB);
        actprep_kernel<<<g, 256>>>(0, side, 256, 128, 128, 256, 19200, 0, 1);
    }

    // 3) conv3x3 over concat -> y11 (fp16)
    dim3 g3(1200, 1, 1);
    conv_mma_kernel<<<g3, 256, SMEM_BYTES>>>(
        /*actSel*/1, 256, 120, 160,
        /*wSel*/1, /*coT*/128, /*multiSet*/0, 0, 9,
        /*outSel*/1, 128,
        1, 0, 1, 0, 160);

    // 4) BN stats on y11 from partials; a11 = relu(bn(y11)) -> fp16 NHWC
    combine_kernel<<<128, 256>>>(0, g11, b11, 2, nullptr, nullptr, 0);
    {
        dim3 g(19200/64, 128/64, BB);
        actprep_kernel<<<g, 256>>>(1, nullptr, 128, 0, 128, 128, 19200, 2, 2);
    }

    // 5) conv3x3 (Cin=128) -> y2 (fp16)
    conv_mma_kernel<<<g3, 256, SMEM_BYTES>>>(
        /*actSel*/2, 128, 120, 160,
        /*wSel*/2, /*coT*/128, /*multiSet*/0, 0, 9,
        /*outSel*/2, 128,
        1, 0, 1, 0, 160);

    // 6) BN stats for y2 from partials; final fuse: relu(bn(y2) + bn(ysc))
    combine_kernel<<<128, 256>>>(0, g2, b2, 3, nullptr, nullptr, 0);
    final_kernel<<<19200, 256>>>(out);
}